// round 5
// baseline (speedup 1.0000x reference)
#include <cuda_runtime.h>
#include <math.h>
#include <stdint.h>

#define BN_EPS 1e-5f

typedef unsigned long long u64;

// ================= helpers =================
__device__ __forceinline__ uint32_t smem_u32_of(const void* p) {
    uint32_t a;
    asm("{ .reg .u64 t; cvta.to.shared.u64 t, %1; cvt.u32.u64 %0, t; }" : "=r"(a) : "l"(p));
    return a;
}

__device__ __forceinline__ void ldsm4(uint32_t* r, uint32_t addr) {
    asm volatile("ldmatrix.sync.aligned.m8n8.x4.shared.b16 {%0,%1,%2,%3}, [%4];"
                 : "=r"(r[0]), "=r"(r[1]), "=r"(r[2]), "=r"(r[3]) : "r"(addr));
}

__device__ __forceinline__ void imma(int* c, const uint32_t* a, uint32_t b0, uint32_t b1) {
    asm volatile(
        "mma.sync.aligned.m16n8k32.row.col.s32.s8.s8.s32 "
        "{%0,%1,%2,%3}, {%4,%5,%6,%7}, {%8,%9}, {%0,%1,%2,%3};"
        : "+r"(c[0]), "+r"(c[1]), "+r"(c[2]), "+r"(c[3])
        : "r"(a[0]), "r"(a[1]), "r"(a[2]), "r"(a[3]), "r"(b0), "r"(b1));
}

#define CP_ASYNC16(dst, src, sz) \
    asm volatile("cp.async.cg.shared.global [%0], [%1], 16, %2;" :: \
        "r"(dst), "l"(src), "r"(sz) : "memory")
#define CP_COMMIT() asm volatile("cp.async.commit_group;" ::: "memory")
#define CP_WAIT(n) asm volatile("cp.async.wait_group %0;" :: "n"(n) : "memory")

// ================= packed f32x2 (SIMT GEMM path) =================
__device__ __forceinline__ u64 pack2(float x) {
    u64 r; asm("mov.b64 %0, {%1, %1};" : "=l"(r) : "f"(x)); return r;
}
__device__ __forceinline__ u64 pack2(float x, float y) {
    u64 r; asm("mov.b64 %0, {%1, %2};" : "=l"(r) : "f"(x), "f"(y)); return r;
}
__device__ __forceinline__ void unpack2(u64 v, float& x, float& y) {
    asm("mov.b64 {%0, %1}, %2;" : "=f"(x), "=f"(y) : "l"(v));
}
__device__ __forceinline__ void fma2(u64& d, u64 a, u64 b) {
    asm("fma.rn.f32x2 %0, %1, %2, %0;" : "+l"(d) : "l"(a), "l"(b));
}
__device__ __forceinline__ float silu_f(float x) { return x / (1.0f + __expf(-x)); }

// ================= static scratch =================
__device__ float g_agg[8192 * 128];
__device__ float g_bufX[8192 * 128];
__device__ float g_bufAa[8192 * 128];
__device__ float g_bufS[8192 * 128];
__device__ float g_nodeA[2048 * 128];
__device__ float g_C[128 * 128];
__device__ float g_d[128];
__device__ char g_qx1[8192 * 128];
__device__ char g_qx0[8192 * 128];
__device__ char g_qa1[8192 * 128];
__device__ char g_qa0[8192 * 128];
__device__ char g_W1q1[3 * 27 * 128 * 128];
__device__ char g_W1q0[3 * 27 * 128 * 128];
__device__ char g_W2q1[3 * 27 * 128 * 128];
__device__ char g_W2q0[3 * 27 * 128 * 128];
__device__ char g_W5q1[3 * 125 * 128 * 128];
__device__ char g_W5q0[3 * 125 * 128 * 128];
__device__ float g_swS[9 * 128];
__device__ unsigned g_sx[8];

// ================= SIMT 64x128x128 MMA core =================
__device__ __forceinline__ void mma_64x128x128(const float* __restrict__ As,
                                               const float* __restrict__ Bs,
                                               u64 acc[4][4], int tid) {
    const int q = tid & 15;
    const int rg = tid >> 4;
    const float* Ar = As + rg * 4 * 128;
    const int n0 = q * 4;
#pragma unroll 4
    for (int k = 0; k < 128; ++k) {
        float4 b0 = *(const float4*)(Bs + k * 128 + n0);
        float4 b1 = *(const float4*)(Bs + k * 128 + n0 + 64);
        u64 B00 = pack2(b0.x, b0.y), B01 = pack2(b0.z, b0.w);
        u64 B10 = pack2(b1.x, b1.y), B11 = pack2(b1.z, b1.w);
#pragma unroll
        for (int i = 0; i < 4; ++i) {
            u64 a = pack2(Ar[i * 128 + k]);
            fma2(acc[i][0], a, B00);
            fma2(acc[i][1], a, B01);
            fma2(acc[i][2], a, B10);
            fma2(acc[i][3], a, B11);
        }
    }
}

// ================= combo gemm: Cm + nodeA =================
__global__ __launch_bounds__(256) void combo_gemm(
    const float* __restrict__ node_embedding, const float* __restrict__ edge_w2,
    const float* __restrict__ msg_w1, float* __restrict__ Cm,
    float* __restrict__ nodeA) {
    extern __shared__ float sm[];
    float* As = sm;
    float* Bs = sm + 64 * 128;
    const int tid = threadIdx.x;
    const float* A;
    const float* W;
    float* Y;
    int row0;
    if (blockIdx.x < 2) {
        A = edge_w2; W = msg_w1 + 128 * 128; Y = Cm; row0 = blockIdx.x * 64;
    } else {
        A = node_embedding; W = msg_w1; Y = nodeA; row0 = (blockIdx.x - 2) * 64;
    }
    const float4* A4 = (const float4*)(A + (size_t)row0 * 128);
    float4* Ad = (float4*)As;
#pragma unroll
    for (int j = 0; j < 8; ++j) Ad[tid + j * 256] = A4[tid + j * 256];
    const float4* W4 = (const float4*)W;
    float4* Bd = (float4*)Bs;
#pragma unroll
    for (int j = 0; j < 16; ++j) Bd[tid + j * 256] = W4[tid + j * 256];
    __syncthreads();

    u64 acc[4][4];
#pragma unroll
    for (int i = 0; i < 4; ++i)
#pragma unroll
        for (int j = 0; j < 4; ++j) acc[i][j] = 0ull;
    mma_64x128x128(As, Bs, acc, tid);

    const int q = tid & 15, rg = tid >> 4, n0 = q * 4;
#pragma unroll
    for (int i = 0; i < 4; ++i) {
        const int v = row0 + rg * 4 + i;
#pragma unroll
        for (int g = 0; g < 2; ++g) {
            const int c0 = n0 + g * 64;
            float r0, r1, r2, r3;
            unpack2(acc[i][g * 2 + 0], r0, r1);
            unpack2(acc[i][g * 2 + 1], r2, r3);
            *(float4*)(Y + (size_t)v * 128 + c0) = make_float4(r0, r1, r2, r3);
        }
    }
}

// ================= fused MLP -> f32 x + max =================
__global__ __launch_bounds__(256) void fused_mlp(
    const float* __restrict__ agg,
    const float* __restrict__ msg_w2, const float* __restrict__ msg_b2,
    const float* __restrict__ upd_w1, const float* __restrict__ upd_b1,
    const float* __restrict__ upd_w2, const float* __restrict__ upd_b2,
    const float* __restrict__ gamma, const float* __restrict__ beta,
    float* __restrict__ Yx, unsigned* __restrict__ maxout) {
    extern __shared__ float sm[];
    __shared__ unsigned redS[256];
    float* As = sm;
    float* Bs = sm + 64 * 128;
    const int tid = threadIdx.x;
    const int row0 = blockIdx.x * 64;
    const int q = tid & 15, rg = tid >> 4, n0 = q * 4;

    {
        const float4* A4 = (const float4*)(agg + (size_t)row0 * 128);
        float4* Ad = (float4*)As;
#pragma unroll
        for (int j = 0; j < 8; ++j) Ad[tid + j * 256] = A4[tid + j * 256];
    }

    const float* Ws[3] = {msg_w2, upd_w1, upd_w2};
    const float* Bv[3] = {msg_b2, upd_b1, upd_b2};
    float lmax = 0.f;

#pragma unroll
    for (int s = 0; s < 3; ++s) {
        const float4* W4 = (const float4*)Ws[s];
        float4* Bd = (float4*)Bs;
#pragma unroll
        for (int j = 0; j < 16; ++j) Bd[tid + j * 256] = W4[tid + j * 256];
        __syncthreads();

        u64 acc[4][4];
#pragma unroll
        for (int i = 0; i < 4; ++i)
#pragma unroll
            for (int j = 0; j < 4; ++j) acc[i][j] = 0ull;
        mma_64x128x128(As, Bs, acc, tid);
        __syncthreads();

        const float* bias = Bv[s];
#pragma unroll
        for (int i = 0; i < 4; ++i) {
            const int r = rg * 4 + i;
#pragma unroll
            for (int g = 0; g < 2; ++g) {
                const int c0 = n0 + g * 64;
                float o0, o1, o2, o3;
                unpack2(acc[i][g * 2 + 0], o0, o1);
                unpack2(acc[i][g * 2 + 1], o2, o3);
                o0 += bias[c0 + 0]; o1 += bias[c0 + 1];
                o2 += bias[c0 + 2]; o3 += bias[c0 + 3];
                if (s == 1) {
                    o0 = silu_f(o0); o1 = silu_f(o1);
                    o2 = silu_f(o2); o3 = silu_f(o3);
                }
                if (s < 2) {
                    *(float4*)(As + r * 128 + c0) = make_float4(o0, o1, o2, o3);
                } else {
                    const float rs = rsqrtf(1.0f + BN_EPS);
                    o0 = o0 * (gamma[c0 + 0] * rs) + beta[c0 + 0];
                    o1 = o1 * (gamma[c0 + 1] * rs) + beta[c0 + 1];
                    o2 = o2 * (gamma[c0 + 2] * rs) + beta[c0 + 2];
                    o3 = o3 * (gamma[c0 + 3] * rs) + beta[c0 + 3];
                    *(float4*)(Yx + (size_t)(row0 + r) * 128 + c0) =
                        make_float4(o0, o1, o2, o3);
                    lmax = fmaxf(lmax, fmaxf(fmaxf(fabsf(o0), fabsf(o1)),
                                             fmaxf(fabsf(o2), fabsf(o3))));
                }
            }
        }
        __syncthreads();
    }
    redS[tid] = __float_as_uint(lmax);
    __syncthreads();
    for (int s = 128; s > 0; s >>= 1) {
        if (tid < s) redS[tid] = max(redS[tid], redS[tid + s]);
        __syncthreads();
    }
    if (tid == 0) atomicMax(maxout, redS[0]);
}

// ================= int8 quantize: f32 -> (q1, q0) limbs =================
__global__ __launch_bounds__(256) void quant_x(
    const float4* __restrict__ X, const unsigned* __restrict__ sxp,
    char4* __restrict__ q1, char4* __restrict__ q0) {
    const int i = blockIdx.x * 256 + threadIdx.x;  // 262144 threads = 1M elems
    const float sx = __uint_as_float(*sxp);
    const float inv = sx > 0.f ? 32512.f / sx : 0.f;
    float4 v = X[i];
    int a = __float2int_rn(v.x * inv);
    int b = __float2int_rn(v.y * inv);
    int c = __float2int_rn(v.z * inv);
    int d = __float2int_rn(v.w * inv);
    int a1 = (a + 128) >> 8, b1 = (b + 128) >> 8, c1 = (c + 128) >> 8, d1 = (d + 128) >> 8;
    q1[i] = make_char4((char)a1, (char)b1, (char)c1, (char)d1);
    q0[i] = make_char4((char)(a - (a1 << 8)), (char)(b - (b1 << 8)),
                       (char)(c - (c1 << 8)), (char)(d - (d1 << 8)));
}

// ================= weight quantize (per-co scale, BN gamma folded) =================
// grid (128 co, 9 mat): mat = kind*3 + blk; kind 0=W1, 1=W2, 2=W5.
__global__ __launch_bounds__(128) void prep_quant_w(
    const float* __restrict__ c1, const float* __restrict__ g1,
    const float* __restrict__ c2, const float* __restrict__ g2,
    const float* __restrict__ c5, const float* __restrict__ g5,
    char* __restrict__ W1q1, char* __restrict__ W1q0,
    char* __restrict__ W2q1, char* __restrict__ W2q0,
    char* __restrict__ W5q1, char* __restrict__ W5q0,
    float* __restrict__ swS) {
    __shared__ float red[128];
    const int mat = blockIdx.y;
    const int blk = mat % 3;
    const int kind = mat / 3;
    const int o = blockIdx.x;
    const int tid = threadIdx.x;
    const float* w;
    float gs;
    char *o1, *o0;
    int T;
    if (kind == 0) {
        T = 27; w = c1 + (size_t)blk * 128 * 128 * 27; gs = g1[blk * 128 + o];
        o1 = W1q1 + (size_t)blk * 27 * 16384; o0 = W1q0 + (size_t)blk * 27 * 16384;
    } else if (kind == 1) {
        T = 27; w = c2 + (size_t)blk * 128 * 128 * 27; gs = g2[blk * 128 + o];
        o1 = W2q1 + (size_t)blk * 27 * 16384; o0 = W2q0 + (size_t)blk * 27 * 16384;
    } else {
        T = 125; w = c5 + (size_t)blk * 128 * 128 * 125; gs = g5[blk * 128 + o];
        o1 = W5q1 + (size_t)blk * 125 * 16384; o0 = W5q0 + (size_t)blk * 125 * 16384;
    }
    const float s = gs * rsqrtf(1.0f + BN_EPS);
    const float* src = w + (size_t)o * 128 * T;
    const int n = 128 * T;
    float mx = 0.f;
    for (int k = tid; k < n; k += 128) mx = fmaxf(mx, fabsf(src[k] * s));
    red[tid] = mx;
    __syncthreads();
    for (int st = 64; st > 0; st >>= 1) {
        if (tid < st) red[tid] = fmaxf(red[tid], red[tid + st]);
        __syncthreads();
    }
    mx = red[0];
    if (tid == 0) swS[mat * 128 + o] = mx / (32512.f * 32512.f);
    const float inv = mx > 0.f ? 32512.f / mx : 0.f;
    for (int k = tid; k < n; k += 128) {
        const int ci = k / T, t = k - ci * T;
        const int q = __float2int_rn(src[k] * s * inv);
        const int h = (q + 128) >> 8;
        const size_t pos = ((size_t)t * 128 + o) * 128 + ci;
        o1[pos] = (char)h;
        o0[pos] = (char)(q - (h << 8));
    }
}

// ================= int8 IMMA conv (implicit GEMM, 3-term 16-bit split) =============
#define CE_F32 0
#define CE_RELU_MAX 1
#define CE_ADDRELU_MAX 2

#define ISTG 49152
#define I_A1 0
#define I_A0 8192
#define I_B1 16384
#define I_B0 32768
#define I_BIAS (2 * ISTG)
#define I_SW (I_BIAS + 512)
#define I_SMEM (I_SW + 512)

template <int KS, int EPI>
__global__ __launch_bounds__(256, 1) void conv_imma(
    const char* __restrict__ Xq1, const char* __restrict__ Xq0,
    const char* __restrict__ Wq1, const char* __restrict__ Wq0,
    const unsigned* __restrict__ sxin, const float* __restrict__ swS,
    const float* __restrict__ bias, const float* __restrict__ addb,
    float* __restrict__ Yf32, unsigned* __restrict__ maxout) {
    extern __shared__ char smc[];
    __shared__ unsigned redS[256];
    const uint32_t sb = smem_u32_of(smc);
    const int tid = threadIdx.x;
    const int lane = tid & 31, wid = tid >> 5;
    constexpr int P = KS / 2;
    constexpr int TAPS = KS * KS * KS;

    const int vbase = blockIdx.x * 64;
    const int y0 = (vbase >> 4) & 15;
    const int z = (vbase >> 8) & 15;
    const int bb = vbase >> 12;

    if (tid < 128) {
        ((float*)(smc + I_BIAS))[tid] = bias[tid];
        ((float*)(smc + I_SW))[tid] = swS[tid];
    }
    const float sxv = __uint_as_float(*sxin);

    auto issue = [&](int tap, int stage) {
        const int dz = tap / (KS * KS);
        const int rem = tap - dz * KS * KS;
        const int dy = rem / KS, dx = rem - dy * KS;
        const int iz = z + dz - P;
        const uint32_t stb = sb + stage * ISTG;
        const bool zok = (iz >= 0) && (iz < 16);
        // A: 64 rows x 128B, q1+q0 -> 512 chunks each... 2 per thread each
#pragma unroll
        for (int i = 0; i < 2; ++i) {
            const int idx = tid + i * 256;
            const int r = idx >> 3, g = idx & 7;
            const int iy = y0 + (r >> 4) + dy - P;
            const int ix = (r & 15) + dx - P;
            const bool ok = zok && (iy >= 0) && (iy < 16) && (ix >= 0) && (ix < 16);
            const int vox = ok ? (((bb * 16 + iz) * 16 + iy) * 16 + ix) : 0;
            const uint32_t srcsz = ok ? 16u : 0u;
            const size_t goff = (size_t)vox * 128 + g * 16;
            const uint32_t rel = r * 128 + ((g ^ (r & 7)) << 4);
            CP_ASYNC16(stb + I_A1 + rel, Xq1 + goff, srcsz);
            CP_ASYNC16(stb + I_A0 + rel, Xq0 + goff, srcsz);
        }
        // B: 128 rows x 128B, q1+q0 -> 1024 chunks each, 4 per thread each
#pragma unroll
        for (int i = 0; i < 4; ++i) {
            const int idx = tid + i * 256;
            const int r = idx >> 3, g = idx & 7;
            const size_t goff = ((size_t)tap * 128 + r) * 128 + g * 16;
            const uint32_t rel = r * 128 + ((g ^ (r & 7)) << 4);
            CP_ASYNC16(stb + I_B1 + rel, Wq1 + goff, 16u);
            CP_ASYNC16(stb + I_B0 + rel, Wq0 + goff, 16u);
        }
        CP_COMMIT();
    };

    int acc11[2][4][4];
    int accC[2][4][4];
#pragma unroll
    for (int i = 0; i < 2; ++i)
#pragma unroll
        for (int j = 0; j < 4; ++j)
#pragma unroll
            for (int k = 0; k < 4; ++k) { acc11[i][j][k] = 0; accC[i][j][k] = 0; }

    const int warp_m = wid >> 2, warp_n = wid & 3;
    uint32_t aRel[2], aXor[2];
#pragma unroll
    for (int ma = 0; ma < 2; ++ma) {
        const int row = warp_m * 32 + ma * 16 + (lane & 15);
        aRel[ma] = row * 128;
        aXor[ma] = row & 7;
    }
    uint32_t bRel[2], bXor[2];
#pragma unroll
    for (int nt = 0; nt < 2; ++nt) {
        const int row = warp_n * 32 + nt * 16 + ((lane >> 4) << 3) + (lane & 7);
        bRel[nt] = row * 128;
        bXor[nt] = row & 7;
    }
    const uint32_t gAsel = lane >> 4;
    const uint32_t gBsel = (lane >> 3) & 1;

    issue(0, 0);
    for (int tap = 0; tap < TAPS; ++tap) {
        if (tap + 1 < TAPS) {
            issue(tap + 1, (tap + 1) & 1);
            CP_WAIT(1);
        } else {
            CP_WAIT(0);
        }
        __syncthreads();
        const uint32_t stb = sb + (tap & 1) * ISTG;
#pragma unroll
        for (int ks = 0; ks < 4; ++ks) {
            uint32_t a1f[2][4], a0f[2][4], b1f[2][4], b0f[2][4];
            const uint32_t gA = ks * 2 + gAsel;
            const uint32_t gB = ks * 2 + gBsel;
#pragma unroll
            for (int ma = 0; ma < 2; ++ma) {
                const uint32_t sw = ((gA ^ aXor[ma]) & 7) << 4;
                ldsm4(a1f[ma], stb + I_A1 + aRel[ma] + sw);
                ldsm4(a0f[ma], stb + I_A0 + aRel[ma] + sw);
            }
#pragma unroll
            for (int nt = 0; nt < 2; ++nt) {
                const uint32_t sw = ((gB ^ bXor[nt]) & 7) << 4;
                ldsm4(b1f[nt], stb + I_B1 + bRel[nt] + sw);
                ldsm4(b0f[nt], stb + I_B0 + bRel[nt] + sw);
            }
#pragma unroll
            for (int ma = 0; ma < 2; ++ma)
#pragma unroll
                for (int nb = 0; nb < 4; ++nb) {
                    const uint32_t p1a = b1f[nb >> 1][(nb & 1) * 2];
                    const uint32_t p1b = b1f[nb >> 1][(nb & 1) * 2 + 1];
                    const uint32_t p0a = b0f[nb >> 1][(nb & 1) * 2];
                    const uint32_t p0b = b0f[nb >> 1][(nb & 1) * 2 + 1];
                    imma(acc11[ma][nb], a1f[ma], p1a, p1b);
                    imma(accC[ma][nb], a1f[ma], p0a, p0b);
                    imma(accC[ma][nb], a0f[ma], p1a, p1b);
                }
        }
        __syncthreads();
    }

    // ---- epilogue ----
    const float* biasS = (const float*)(smc + I_BIAS);
    const float* swSs = (const float*)(smc + I_SW);
    float lmax = 0.f;
#pragma unroll
    for (int ma = 0; ma < 2; ++ma) {
        const int r0 = vbase + warp_m * 32 + ma * 16 + (lane >> 2);
#pragma unroll
        for (int half = 0; half < 2; ++half) {
            const int v = r0 + half * 8;
#pragma unroll
            for (int nb = 0; nb < 4; ++nb) {
                const int c = warp_n * 32 + nb * 8 + (lane & 3) * 2;
                const float f0 = sxv * swSs[c];
                const float f1 = sxv * swSs[c + 1];
                float o0 = f0 * ((float)acc11[ma][nb][half * 2 + 0] * 65536.f +
                                 (float)accC[ma][nb][half * 2 + 0] * 256.f) + biasS[c];
                float o1 = f1 * ((float)acc11[ma][nb][half * 2 + 1] * 65536.f +
                                 (float)accC[ma][nb][half * 2 + 1] * 256.f) + biasS[c + 1];
                if (EPI == CE_ADDRELU_MAX) {
                    const float2 a = *(const float2*)(addb + (size_t)v * 128 + c);
                    o0 += a.x;
                    o1 += a.y;
                }
                if (EPI != CE_F32) {
                    o0 = fmaxf(o0, 0.f);
                    o1 = fmaxf(o1, 0.f);
                    lmax = fmaxf(lmax, fmaxf(o0, o1));
                }
                *(float2*)(Yf32 + (size_t)v * 128 + c) = make_float2(o0, o1);
            }
        }
    }
    if (EPI != CE_F32) {
        redS[tid] = __float_as_uint(lmax);
        __syncthreads();
        for (int s = 128; s > 0; s >>= 1) {
            if (tid < s) redS[tid] = max(redS[tid], redS[tid + s]);
            __syncthreads();
        }
        if (tid == 0) atomicMax(maxout, redS[0]);
    }
}

// ================= edge kernel =================
__global__ __launch_bounds__(256) void edge_kernel(
    const float* __restrict__ node_pos, const float* __restrict__ grid_pos,
    const int* __restrict__ erow, const int* __restrict__ ecol,
    const float* __restrict__ ew1, const float* __restrict__ eb1,
    const float* __restrict__ Cmat, const float* __restrict__ dvec,
    const float* __restrict__ nodeA, float* __restrict__ agg) {
    extern __shared__ float sm[];
    float* uS = sm;
    float* Bs = sm + 8192;
    float* hS = sm + 8192 + 16384;
    float* attr = hS + 8192;
    int* rowS = (int*)(attr + 64 * 6);
    const int tid = threadIdx.x;
    const int ebase = blockIdx.x * 64;

    const float4* C4 = (const float4*)Cmat;
    float4* Bd = (float4*)Bs;
#pragma unroll
    for (int j = 0; j < 16; ++j) Bd[tid + j * 256] = C4[tid + j * 256];

    if (tid < 64) {
        const int e = ebase + tid;
        const int r = erow[e];
        const int c = ecol[e];
        rowS[tid] = r;
        attr[tid * 6 + 0] = node_pos[r * 3 + 0];
        attr[tid * 6 + 1] = node_pos[r * 3 + 1];
        attr[tid * 6 + 2] = node_pos[r * 3 + 2];
        attr[tid * 6 + 3] = grid_pos[c * 3 + 0];
        attr[tid * 6 + 4] = grid_pos[c * 3 + 1];
        attr[tid * 6 + 5] = grid_pos[c * 3 + 2];
    }
    __syncthreads();

    for (int idx = tid; idx < 64 * 128; idx += 256) {
        const int e = idx >> 7, j = idx & 127;
        float s = eb1[j];
        const float* a = attr + e * 6;
#pragma unroll
        for (int i = 0; i < 6; ++i) s += a[i] * ew1[i * 128 + j];
        uS[idx] = silu_f(s);
    }
    __syncthreads();

    u64 acc[4][4];
#pragma unroll
    for (int i = 0; i < 4; ++i)
#pragma unroll
        for (int j = 0; j < 4; ++j) acc[i][j] = 0ull;
    mma_64x128x128(uS, Bs, acc, tid);

    const int q = tid & 15, rg = tid >> 4, n0 = q * 4;
#pragma unroll
    for (int i = 0; i < 4; ++i) {
        const int e = rg * 4 + i;
        const float* na = nodeA + (size_t)rowS[e] * 128;
#pragma unroll
        for (int g = 0; g < 2; ++g) {
            const int c0 = n0 + g * 64;
            float r0, r1, r2, r3;
            unpack2(acc[i][g * 2 + 0], r0, r1);
            unpack2(acc[i][g * 2 + 1], r2, r3);
            float4 o;
            o.x = silu_f(r0 + na[c0 + 0] + dvec[c0 + 0]);
            o.y = silu_f(r1 + na[c0 + 1] + dvec[c0 + 1]);
            o.z = silu_f(r2 + na[c0 + 2] + dvec[c0 + 2]);
            o.w = silu_f(r3 + na[c0 + 3] + dvec[c0 + 3]);
            *(float4*)(hS + e * 128 + c0) = o;
        }
    }
    __syncthreads();

    for (int idx = tid; idx < 8 * 128; idx += 256) {
        const int g = idx >> 7, c = idx & 127;
        float s = 0.f;
#pragma unroll
        for (int j = 0; j < 8; ++j) s += hS[(g * 8 + j) * 128 + c];
        agg[(size_t)(blockIdx.x * 8 + g) * 128 + c] = s * 0.125f;
    }
}

// ================= prep d =================
__global__ void prep_d_kernel(const float* __restrict__ eb2,
                              const float* __restrict__ mw1,
                              const float* __restrict__ mb1,
                              float* __restrict__ dvec) {
    const int n = threadIdx.x;
    float s = mb1[n];
    for (int k = 0; k < 128; ++k) s += eb2[k] * mw1[(128 + k) * 128 + n];
    dvec[n] = s;
}

// ================= pool + fc + log_softmax =================
__global__ __launch_bounds__(512) void pool_fc_kernel(
    const float* __restrict__ X, const float* __restrict__ fcw,
    const float* __restrict__ fcb, float* __restrict__ out) {
    __shared__ float part[4][128];
    __shared__ float logits[20];
    const int b = blockIdx.x, tid = threadIdx.x;
    const int c = tid & 127, ch = tid >> 7;
    const float* Xb = X + (size_t)b * 4096 * 128;
    float m0 = -1e30f, m1 = -1e30f, m2 = -1e30f, m3 = -1e30f;
    const int v0 = ch * 1024;
    for (int v = 0; v < 1024; v += 4) {
        m0 = fmaxf(m0, Xb[(size_t)(v0 + v + 0) * 128 + c]);
        m1 = fmaxf(m1, Xb[(size_t)(v0 + v + 1) * 128 + c]);
        m2 = fmaxf(m2, Xb[(size_t)(v0 + v + 2) * 128 + c]);
        m3 = fmaxf(m3, Xb[(size_t)(v0 + v + 3) * 128 + c]);
    }
    part[ch][c] = fmaxf(fmaxf(m0, m1), fmaxf(m2, m3));
    __syncthreads();
    if (tid < 128) {
        part[0][tid] = fmaxf(fmaxf(part[0][tid], part[1][tid]),
                             fmaxf(part[2][tid], part[3][tid]));
    }
    __syncthreads();
    if (tid < 20) {
        float s = fcb[tid];
        for (int k = 0; k < 128; ++k) s += part[0][k] * fcw[k * 20 + tid];
        logits[tid] = s;
    }
    __syncthreads();
    if (tid == 0) {
        float mx = logits[0];
        for (int j = 1; j < 20; ++j) mx = fmaxf(mx, logits[j]);
        float se = 0.f;
        for (int j = 0; j < 20; ++j) se += expf(logits[j] - mx);
        const float lse = logf(se) + mx;
        for (int j = 0; j < 20; ++j) out[b * 20 + j] = logits[j] - lse;
    }
}

// ================= host launch =================
extern "C" void kernel_launch(void* const* d_in, const int* in_sizes, int n_in,
                              void* d_out, int out_size) {
    const float* node_embedding = (const float*)d_in[0];
    const float* node_pos = (const float*)d_in[1];
    const float* grid_pos = (const float*)d_in[2];
    const int* edge_row = (const int*)d_in[3];
    const int* edge_col = (const int*)d_in[4];
    const float* edge_w1 = (const float*)d_in[5];
    const float* edge_b1 = (const float*)d_in[6];
    const float* edge_w2 = (const float*)d_in[7];
    const float* edge_b2 = (const float*)d_in[8];
    const float* msg_w1 = (const float*)d_in[9];
    const float* msg_b1 = (const float*)d_in[10];
    const float* msg_w2 = (const float*)d_in[11];
    const float* msg_b2 = (const float*)d_in[12];
    const float* upd_w1 = (const float*)d_in[13];
    const float* upd_b1 = (const float*)d_in[14];
    const float* upd_w2 = (const float*)d_in[15];
    const float* upd_b2 = (const float*)d_in[16];
    const float* in_gamma = (const float*)d_in[17];
    const float* in_beta = (const float*)d_in[18];
    const float* blk_conv1 = (const float*)d_in[19];
    const float* blk_bn1_g = (const float*)d_in[20];
    const float* blk_bn1_b = (const float*)d_in[21];
    const float* blk_conv2 = (const float*)d_in[22];
    const float* blk_bn2_g = (const float*)d_in[23];
    const float* blk_bn2_b = (const float*)d_in[24];
    const float* blk_conv5 = (const float*)d_in[25];
    const float* blk_bns_g = (const float*)d_in[26];
    const float* blk_bns_b = (const float*)d_in[27];
    const float* fc_w = (const float*)d_in[28];
    const float* fc_b = (const float*)d_in[29];
    float* out = (float*)d_out;

    float *agg, *bufX, *bufAa, *bufS, *nodeA, *Cm, *dv, *swS;
    char *qx1, *qx0, *qa1, *qa0;
    char *W1q1, *W1q0, *W2q1, *W2q0, *W5q1, *W5q0;
    unsigned* sx;
    cudaGetSymbolAddress((void**)&agg, g_agg);
    cudaGetSymbolAddress((void**)&bufX, g_bufX);
    cudaGetSymbolAddress((void**)&bufAa, g_bufAa);
    cudaGetSymbolAddress((void**)&bufS, g_bufS);
    cudaGetSymbolAddress((void**)&nodeA, g_nodeA);
    cudaGetSymbolAddress((void**)&Cm, g_C);
    cudaGetSymbolAddress((void**)&dv, g_d);
    cudaGetSymbolAddress((void**)&swS, g_swS);
    cudaGetSymbolAddress((void**)&qx1, g_qx1);
    cudaGetSymbolAddress((void**)&qx0, g_qx0);
    cudaGetSymbolAddress((void**)&qa1, g_qa1);
    cudaGetSymbolAddress((void**)&qa0, g_qa0);
    cudaGetSymbolAddress((void**)&W1q1, g_W1q1);
    cudaGetSymbolAddress((void**)&W1q0, g_W1q0);
    cudaGetSymbolAddress((void**)&W2q1, g_W2q1);
    cudaGetSymbolAddress((void**)&W2q0, g_W2q0);
    cudaGetSymbolAddress((void**)&W5q1, g_W5q1);
    cudaGetSymbolAddress((void**)&W5q0, g_W5q0);
    cudaGetSymbolAddress((void**)&sx, g_sx);

    const int SMEM_GEMM = (64 * 128 + 128 * 128) * 4;
    const int SMEM_EDGE = (8192 + 16384 + 8192 + 384) * 4 + 64 * 4;

    cudaFuncSetAttribute(combo_gemm, cudaFuncAttributeMaxDynamicSharedMemorySize, SMEM_GEMM);
    cudaFuncSetAttribute(fused_mlp, cudaFuncAttributeMaxDynamicSharedMemorySize, SMEM_GEMM);
    cudaFuncSetAttribute(edge_kernel, cudaFuncAttributeMaxDynamicSharedMemorySize, SMEM_EDGE);
    cudaFuncSetAttribute(conv_imma<3, CE_RELU_MAX>, cudaFuncAttributeMaxDynamicSharedMemorySize, I_SMEM);
    cudaFuncSetAttribute(conv_imma<3, CE_ADDRELU_MAX>, cudaFuncAttributeMaxDynamicSharedMemorySize, I_SMEM);
    cudaFuncSetAttribute(conv_imma<5, CE_F32>, cudaFuncAttributeMaxDynamicSharedMemorySize, I_SMEM);

    cudaMemsetAsync(sx, 0, 8 * sizeof(unsigned));

    // k0..k3 (ncu profiles #3 -> fused_mlp)
    combo_gemm<<<34, 256, SMEM_GEMM>>>(node_embedding, edge_w2, msg_w1, Cm, nodeA);
    prep_d_kernel<<<1, 128>>>(edge_b2, msg_w1, msg_b1, dv);
    edge_kernel<<<1024, 256, SMEM_EDGE>>>(node_pos, grid_pos, edge_row, edge_col,
                                          edge_w1, edge_b1, Cm, dv, nodeA, agg);
    fused_mlp<<<128, 256, SMEM_GEMM>>>(agg, msg_w2, msg_b2, upd_w1, upd_b1,
                                       upd_w2, upd_b2, in_gamma, in_beta, bufX, sx + 0);
    prep_quant_w<<<dim3(128, 9), 128>>>(blk_conv1, blk_bn1_g, blk_conv2, blk_bn2_g,
                                        blk_conv5, blk_bns_g, W1q1, W1q0, W2q1, W2q0,
                                        W5q1, W5q0, swS);
    quant_x<<<1024, 256>>>((const float4*)bufX, sx + 0, (char4*)qx1, (char4*)qx0);

    for (int i = 0; i < 3; ++i) {
        conv_imma<5, CE_F32><<<128, 256, I_SMEM>>>(
            qx1, qx0, W5q1 + (size_t)i * 125 * 16384, W5q0 + (size_t)i * 125 * 16384,
            sx + 2 * i, swS + (6 + i) * 128, blk_bns_b + i * 128, nullptr, bufS, sx + 7);
        conv_imma<3, CE_RELU_MAX><<<128, 256, I_SMEM>>>(
            qx1, qx0, W1q1 + (size_t)i * 27 * 16384, W1q0 + (size_t)i * 27 * 16384,
            sx + 2 * i, swS + (0 + i) * 128, blk_bn1_b + i * 128, nullptr, bufAa,
            sx + 2 * i + 1);
        quant_x<<<1024, 256>>>((const float4*)bufAa, sx + 2 * i + 1, (char4*)qa1,
                               (char4*)qa0);
        conv_imma<3, CE_ADDRELU_MAX><<<128, 256, I_SMEM>>>(
            qa1, qa0, W2q1 + (size_t)i * 27 * 16384, W2q0 + (size_t)i * 27 * 16384,
            sx + 2 * i + 1, swS + (3 + i) * 128, blk_bn2_b + i * 128, bufS, bufX,
            sx + 2 * (i + 1));
        if (i < 2)
            quant_x<<<1024, 256>>>((const float4*)bufX, sx + 2 * (i + 1), (char4*)qx1,
                                   (char4*)qx0);
    }

    pool_fc_kernel<<<2, 512>>>(bufX, fc_w, fc_b, out);
    (void)in_sizes; (void)n_in; (void)out_size;
}

// round 6
// speedup vs baseline: 2.6840x; 2.6840x over previous
#include <cuda_runtime.h>
#include <cuda_bf16.h>
#include <math.h>
#include <stdint.h>

#define BN_EPS 1e-5f

typedef unsigned long long u64;

// ================= helpers =================
__device__ __forceinline__ uint32_t smem_u32_of(const void* p) {
    uint32_t a;
    asm("{ .reg .u64 t; cvta.to.shared.u64 t, %1; cvt.u32.u64 %0, t; }" : "=r"(a) : "l"(p));
    return a;
}

__device__ __forceinline__ void ldsm4(uint32_t* r, uint32_t addr) {
    asm volatile("ldmatrix.sync.aligned.m8n8.x4.shared.b16 {%0,%1,%2,%3}, [%4];"
                 : "=r"(r[0]), "=r"(r[1]), "=r"(r[2]), "=r"(r[3]) : "r"(addr));
}

__device__ __forceinline__ void mma16816(float* c, const uint32_t* a, uint32_t b0, uint32_t b1) {
    asm volatile(
        "mma.sync.aligned.m16n8k16.row.col.f32.bf16.bf16.f32 "
        "{%0,%1,%2,%3}, {%4,%5,%6,%7}, {%8,%9}, {%0,%1,%2,%3};"
        : "+f"(c[0]), "+f"(c[1]), "+f"(c[2]), "+f"(c[3])
        : "r"(a[0]), "r"(a[1]), "r"(a[2]), "r"(a[3]), "r"(b0), "r"(b1));
}

// .cg for streaming (weights, no reuse) — bypasses L1.
#define CP_ASYNC16_CG(dst, src, sz) \
    asm volatile("cp.async.cg.shared.global [%0], [%1], 16, %2;" :: \
        "r"(dst), "l"(src), "r"(sz) : "memory")
// .ca for activations (25x tap-overlap reuse) — L1-cached.
#define CP_ASYNC16_CA(dst, src, sz) \
    asm volatile("cp.async.ca.shared.global [%0], [%1], 16, %2;" :: \
        "r"(dst), "l"(src), "r"(sz) : "memory")
#define CP_COMMIT() asm volatile("cp.async.commit_group;" ::: "memory")
#define CP_WAIT(n) asm volatile("cp.async.wait_group %0;" :: "n"(n) : "memory")

// ================= packed f32x2 (SIMT GEMM path) =================
__device__ __forceinline__ u64 pack2(float x) {
    u64 r; asm("mov.b64 %0, {%1, %1};" : "=l"(r) : "f"(x)); return r;
}
__device__ __forceinline__ u64 pack2(float x, float y) {
    u64 r; asm("mov.b64 %0, {%1, %2};" : "=l"(r) : "f"(x), "f"(y)); return r;
}
__device__ __forceinline__ void unpack2(u64 v, float& x, float& y) {
    asm("mov.b64 {%0, %1}, %2;" : "=f"(x), "=f"(y) : "l"(v));
}
__device__ __forceinline__ void fma2(u64& d, u64 a, u64 b) {
    asm("fma.rn.f32x2 %0, %1, %2, %0;" : "+l"(d) : "l"(a), "l"(b));
}
__device__ __forceinline__ float silu_f(float x) { return x / (1.0f + __expf(-x)); }

// ================= static scratch =================
__device__ float g_bufA[8192 * 128];
__device__ float g_bufB[8192 * 128];
__device__ float g_bufD[8192 * 128];
__device__ float g_nodeA[2048 * 128];
__device__ float g_C[128 * 128];
__device__ float g_d[128];
__device__ __nv_bfloat16 g_xhiA[8192 * 128];
__device__ __nv_bfloat16 g_xloA[8192 * 128];
__device__ __nv_bfloat16 g_xhiB[8192 * 128];
__device__ __nv_bfloat16 g_xloB[8192 * 128];
__device__ __nv_bfloat16 g_ahi[8192 * 128];
__device__ __nv_bfloat16 g_alo[8192 * 128];
__device__ __nv_bfloat16 g_W1hi[3 * 27 * 128 * 128];
__device__ __nv_bfloat16 g_W1lo[3 * 27 * 128 * 128];
__device__ __nv_bfloat16 g_W2hi[3 * 27 * 128 * 128];
__device__ __nv_bfloat16 g_W2lo[3 * 27 * 128 * 128];
__device__ __nv_bfloat16 g_W5hi[3 * 125 * 128 * 128];
__device__ __nv_bfloat16 g_W5lo[3 * 125 * 128 * 128];

// ================= SIMT 64x128x128 MMA core (smem B) =================
__device__ __forceinline__ void mma_64x128x128(const float* __restrict__ As,
                                               const float* __restrict__ Bs,
                                               u64 acc[4][4], int tid) {
    const int q = tid & 15;
    const int rg = tid >> 4;
    const float* Ar = As + rg * 4 * 128;
    const int n0 = q * 4;
#pragma unroll 4
    for (int k = 0; k < 128; ++k) {
        float4 b0 = *(const float4*)(Bs + k * 128 + n0);
        float4 b1 = *(const float4*)(Bs + k * 128 + n0 + 64);
        u64 B00 = pack2(b0.x, b0.y), B01 = pack2(b0.z, b0.w);
        u64 B10 = pack2(b1.x, b1.y), B11 = pack2(b1.z, b1.w);
#pragma unroll
        for (int i = 0; i < 4; ++i) {
            u64 a = pack2(Ar[i * 128 + k]);
            fma2(acc[i][0], a, B00);
            fma2(acc[i][1], a, B01);
            fma2(acc[i][2], a, B10);
            fma2(acc[i][3], a, B11);
        }
    }
}

// ================= combo gemm: Cm (2) + nodeA (32) + dvec (block 34) =========
__global__ __launch_bounds__(256) void combo_gemm(
    const float* __restrict__ node_embedding, const float* __restrict__ edge_w2,
    const float* __restrict__ msg_w1, const float* __restrict__ eb2,
    const float* __restrict__ mb1, float* __restrict__ Cm,
    float* __restrict__ nodeA, float* __restrict__ dvec) {
    extern __shared__ float sm[];
    float* As = sm;
    float* Bs = sm + 64 * 128;
    const int tid = threadIdx.x;

    if (blockIdx.x == 34) {
        if (tid < 128) {
            const int n = tid;
            float s = mb1[n];
            for (int k = 0; k < 128; ++k) s += eb2[k] * msg_w1[(128 + k) * 128 + n];
            dvec[n] = s;
        }
        return;
    }

    const float* A;
    const float* W;
    float* Y;
    int row0;
    if (blockIdx.x < 2) {
        A = edge_w2; W = msg_w1 + 128 * 128; Y = Cm; row0 = blockIdx.x * 64;
    } else {
        A = node_embedding; W = msg_w1; Y = nodeA; row0 = (blockIdx.x - 2) * 64;
    }
    const float4* A4 = (const float4*)(A + (size_t)row0 * 128);
    float4* Ad = (float4*)As;
#pragma unroll
    for (int j = 0; j < 8; ++j) Ad[tid + j * 256] = A4[tid + j * 256];
    const float4* W4 = (const float4*)W;
    float4* Bd = (float4*)Bs;
#pragma unroll
    for (int j = 0; j < 16; ++j) Bd[tid + j * 256] = W4[tid + j * 256];
    __syncthreads();

    u64 acc[4][4];
#pragma unroll
    for (int i = 0; i < 4; ++i)
#pragma unroll
        for (int j = 0; j < 4; ++j) acc[i][j] = 0ull;
    mma_64x128x128(As, Bs, acc, tid);

    const int q = tid & 15, rg = tid >> 4, n0 = q * 4;
#pragma unroll
    for (int i = 0; i < 4; ++i) {
        const int v = row0 + rg * 4 + i;
#pragma unroll
        for (int g = 0; g < 2; ++g) {
            const int c0 = n0 + g * 64;
            float r0, r1, r2, r3;
            unpack2(acc[i][g * 2 + 0], r0, r1);
            unpack2(acc[i][g * 2 + 1], r2, r3);
            *(float4*)(Y + (size_t)v * 128 + c0) = make_float4(r0, r1, r2, r3);
        }
    }
}

// ================= fused MLP: agg -> msg_w2 -> silu(upd1) -> upd2 -> BN -> split ====
__global__ __launch_bounds__(256) void fused_mlp(
    const float* __restrict__ agg,
    const float* __restrict__ msg_w2, const float* __restrict__ msg_b2,
    const float* __restrict__ upd_w1, const float* __restrict__ upd_b1,
    const float* __restrict__ upd_w2, const float* __restrict__ upd_b2,
    const float* __restrict__ gamma, const float* __restrict__ beta,
    __nv_bfloat16* __restrict__ Yhi, __nv_bfloat16* __restrict__ Ylo) {
    extern __shared__ float sm[];
    float* As = sm;
    float* Bs = sm + 64 * 128;
    const int tid = threadIdx.x;
    const int row0 = blockIdx.x * 64;
    const int q = tid & 15, rg = tid >> 4, n0 = q * 4;

    {
        const float4* A4 = (const float4*)(agg + (size_t)row0 * 128);
        float4* Ad = (float4*)As;
#pragma unroll
        for (int j = 0; j < 8; ++j) Ad[tid + j * 256] = A4[tid + j * 256];
    }

    const float* Ws[3] = {msg_w2, upd_w1, upd_w2};
    const float* Bv[3] = {msg_b2, upd_b1, upd_b2};

#pragma unroll
    for (int s = 0; s < 3; ++s) {
        const float4* W4 = (const float4*)Ws[s];
        float4* Bd = (float4*)Bs;
#pragma unroll
        for (int j = 0; j < 16; ++j) Bd[tid + j * 256] = W4[tid + j * 256];
        __syncthreads();

        u64 acc[4][4];
#pragma unroll
        for (int i = 0; i < 4; ++i)
#pragma unroll
            for (int j = 0; j < 4; ++j) acc[i][j] = 0ull;
        mma_64x128x128(As, Bs, acc, tid);
        __syncthreads();

        const float* bias = Bv[s];
#pragma unroll
        for (int i = 0; i < 4; ++i) {
            const int r = rg * 4 + i;
#pragma unroll
            for (int g = 0; g < 2; ++g) {
                const int c0 = n0 + g * 64;
                float o0, o1, o2, o3;
                unpack2(acc[i][g * 2 + 0], o0, o1);
                unpack2(acc[i][g * 2 + 1], o2, o3);
                o0 += bias[c0 + 0]; o1 += bias[c0 + 1];
                o2 += bias[c0 + 2]; o3 += bias[c0 + 3];
                if (s == 1) {
                    o0 = silu_f(o0); o1 = silu_f(o1);
                    o2 = silu_f(o2); o3 = silu_f(o3);
                }
                if (s < 2) {
                    *(float4*)(As + r * 128 + c0) = make_float4(o0, o1, o2, o3);
                } else {
                    const float rs = rsqrtf(1.0f + BN_EPS);
                    o0 = o0 * (gamma[c0 + 0] * rs) + beta[c0 + 0];
                    o1 = o1 * (gamma[c0 + 1] * rs) + beta[c0 + 1];
                    o2 = o2 * (gamma[c0 + 2] * rs) + beta[c0 + 2];
                    o3 = o3 * (gamma[c0 + 3] * rs) + beta[c0 + 3];
                    __nv_bfloat16 h0 = __float2bfloat16(o0), h1 = __float2bfloat16(o1);
                    __nv_bfloat16 h2 = __float2bfloat16(o2), h3 = __float2bfloat16(o3);
                    __nv_bfloat16 l0 = __float2bfloat16(o0 - __bfloat162float(h0));
                    __nv_bfloat16 l1 = __float2bfloat16(o1 - __bfloat162float(h1));
                    __nv_bfloat16 l2 = __float2bfloat16(o2 - __bfloat162float(h2));
                    __nv_bfloat16 l3 = __float2bfloat16(o3 - __bfloat162float(h3));
                    __nv_bfloat162 hp0 = __halves2bfloat162(h0, h1);
                    __nv_bfloat162 hp1 = __halves2bfloat162(h2, h3);
                    __nv_bfloat162 lp0 = __halves2bfloat162(l0, l1);
                    __nv_bfloat162 lp1 = __halves2bfloat162(l2, l3);
                    const int v = row0 + r;
                    *(uint2*)(Yhi + (size_t)v * 128 + c0) =
                        make_uint2(*(uint32_t*)&hp0, *(uint32_t*)&hp1);
                    *(uint2*)(Ylo + (size_t)v * 128 + c0) =
                        make_uint2(*(uint32_t*)&lp0, *(uint32_t*)&lp1);
                }
            }
        }
        __syncthreads();
    }
}

// ================= tensor-core conv via mma.sync (3-term bf16 split) =================
#define E_RELU_SPLIT 0
#define E_F32 1
#define E_ADDRELU_SPLIT_F32 2

#define CSTG 98304
#define C_AHI 0
#define C_ALO 16384
#define C_BHI 32768
#define C_BLO 65536
#define C_BIAS (2 * CSTG)
#define C_SMEM (C_BIAS + 512)

template <int KS, int EPI>
__global__ __launch_bounds__(256, 1) void conv_mma(
    const __nv_bfloat16* __restrict__ Xhi, const __nv_bfloat16* __restrict__ Xlo,
    const __nv_bfloat16* __restrict__ Whi, const __nv_bfloat16* __restrict__ Wlo,
    const float* __restrict__ bias, const float* __restrict__ addb,
    float* __restrict__ Yf32, __nv_bfloat16* __restrict__ Yhi,
    __nv_bfloat16* __restrict__ Ylo) {
    extern __shared__ char smc[];
    const uint32_t sb = smem_u32_of(smc);
    const int tid = threadIdx.x;
    const int lane = tid & 31, wid = tid >> 5;
    constexpr int P = KS / 2;
    constexpr int TAPS = KS * KS * KS;

    const int vbase = blockIdx.x * 64;
    const int y0 = (vbase >> 4) & 15;
    const int z = (vbase >> 8) & 15;
    const int bb = vbase >> 12;

    if (tid < 128) ((float*)(smc + C_BIAS))[tid] = bias[tid];

    auto issue = [&](int tap, int stage) {
        const int dz = tap / (KS * KS);
        const int rem = tap - dz * KS * KS;
        const int dy = rem / KS, dx = rem - dy * KS;
        const int iz = z + dz - P;
        const uint32_t stb = sb + stage * CSTG;
        const bool zok = (iz >= 0) && (iz < 16);
#pragma unroll
        for (int i = 0; i < 4; ++i) {
            const int ga = tid + i * 256;
            const int r = ga >> 4, g = ga & 15;
            const int iy = y0 + (r >> 4) + dy - P;
            const int ix = (r & 15) + dx - P;
            const bool ok = zok && (iy >= 0) && (iy < 16) && (ix >= 0) && (ix < 16);
            const int vox = ok ? (((bb * 16 + iz) * 16 + iy) * 16 + ix) : 0;
            const uint32_t srcsz = ok ? 16u : 0u;
            const size_t goff = (size_t)vox * 128 + g * 8;
            const uint32_t rel = r * 256 + (((uint32_t)(((g ^ r) & 7) | (g & 8))) << 4);
            CP_ASYNC16_CA(stb + C_AHI + rel, Xhi + goff, srcsz);
            CP_ASYNC16_CA(stb + C_ALO + rel, Xlo + goff, srcsz);
        }
#pragma unroll
        for (int i = 0; i < 8; ++i) {
            const int gb = tid + i * 256;
            const int r = gb >> 4, g = gb & 15;
            const size_t goff = ((size_t)tap * 128 + r) * 128 + g * 8;
            const uint32_t rel = r * 256 + (((uint32_t)(((g ^ r) & 7) | (g & 8))) << 4);
            CP_ASYNC16_CG(stb + C_BHI + rel, Whi + goff, 16u);
            CP_ASYNC16_CG(stb + C_BLO + rel, Wlo + goff, 16u);
        }
        CP_COMMIT();
    };

    float acc[2][4][4];
#pragma unroll
    for (int i = 0; i < 2; ++i)
#pragma unroll
        for (int j = 0; j < 4; ++j)
#pragma unroll
            for (int k = 0; k < 4; ++k) acc[i][j][k] = 0.f;

    const int warp_m = wid >> 2, warp_n = wid & 3;
    uint32_t aRel[2], aXor[2];
#pragma unroll
    for (int ma = 0; ma < 2; ++ma) {
        const int row = warp_m * 32 + ma * 16 + (lane & 15);
        aRel[ma] = row * 256;
        aXor[ma] = row & 7;
    }
    uint32_t bRel[2], bXor[2];
#pragma unroll
    for (int nt = 0; nt < 2; ++nt) {
        const int row = warp_n * 32 + nt * 16 + ((lane >> 4) << 3) + (lane & 7);
        bRel[nt] = row * 256;
        bXor[nt] = row & 7;
    }
    const uint32_t gAsel = lane >> 4;
    const uint32_t gBsel = (lane >> 3) & 1;

    issue(0, 0);
    for (int tap = 0; tap < TAPS; ++tap) {
        // wait for this tap's data; single barrier also protects the stage
        // that issue(tap+1) will overwrite (computed at tap-1).
        CP_WAIT(0);
        __syncthreads();
        if (tap + 1 < TAPS) issue(tap + 1, (tap + 1) & 1);

        const uint32_t stb = sb + (tap & 1) * CSTG;
#pragma unroll
        for (int ks = 0; ks < 8; ++ks) {
            uint32_t aH[2][4], aL[2][4], bH[2][4], bL[2][4];
            const uint32_t gA = ks * 2 + gAsel;
            const uint32_t gB = ks * 2 + gBsel;
#pragma unroll
            for (int ma = 0; ma < 2; ++ma) {
                const uint32_t sw = (((gA ^ aXor[ma]) & 7) | (gA & 8)) << 4;
                ldsm4(aH[ma], stb + C_AHI + aRel[ma] + sw);
                ldsm4(aL[ma], stb + C_ALO + aRel[ma] + sw);
            }
#pragma unroll
            for (int nt = 0; nt < 2; ++nt) {
                const uint32_t sw = (((gB ^ bXor[nt]) & 7) | (gB & 8)) << 4;
                ldsm4(bH[nt], stb + C_BHI + bRel[nt] + sw);
                ldsm4(bL[nt], stb + C_BLO + bRel[nt] + sw);
            }
#pragma unroll
            for (int ma = 0; ma < 2; ++ma)
#pragma unroll
                for (int nb = 0; nb < 4; ++nb) {
                    const uint32_t b0h = bH[nb >> 1][(nb & 1) * 2];
                    const uint32_t b1h = bH[nb >> 1][(nb & 1) * 2 + 1];
                    const uint32_t b0l = bL[nb >> 1][(nb & 1) * 2];
                    const uint32_t b1l = bL[nb >> 1][(nb & 1) * 2 + 1];
                    mma16816(acc[ma][nb], aH[ma], b0h, b1h);
                    mma16816(acc[ma][nb], aH[ma], b0l, b1l);
                    mma16816(acc[ma][nb], aL[ma], b0h, b1h);
                }
        }
    }

    // ---- epilogue ----
    const float* biasS = (const float*)(smc + C_BIAS);
#pragma unroll
    for (int ma = 0; ma < 2; ++ma) {
        const int r0 = vbase + warp_m * 32 + ma * 16 + (lane >> 2);
#pragma unroll
        for (int half = 0; half < 2; ++half) {
            const int v = r0 + half * 8;
#pragma unroll
            for (int nb = 0; nb < 4; ++nb) {
                const int c = warp_n * 32 + nb * 8 + (lane & 3) * 2;
                float o0 = acc[ma][nb][half * 2 + 0] + biasS[c];
                float o1 = acc[ma][nb][half * 2 + 1] + biasS[c + 1];
                if (EPI == E_ADDRELU_SPLIT_F32) {
                    const float2 a = *(const float2*)(addb + (size_t)v * 128 + c);
                    o0 += a.x;
                    o1 += a.y;
                }
                if (EPI != E_F32) {
                    o0 = fmaxf(o0, 0.f);
                    o1 = fmaxf(o1, 0.f);
                }
                if (EPI != E_RELU_SPLIT)
                    *(float2*)(Yf32 + (size_t)v * 128 + c) = make_float2(o0, o1);
                if (EPI != E_F32) {
                    __nv_bfloat16 h0 = __float2bfloat16(o0);
                    __nv_bfloat16 h1 = __float2bfloat16(o1);
                    __nv_bfloat16 l0 = __float2bfloat16(o0 - __bfloat162float(h0));
                    __nv_bfloat16 l1 = __float2bfloat16(o1 - __bfloat162float(h1));
                    __nv_bfloat162 hp = __halves2bfloat162(h0, h1);
                    __nv_bfloat162 lp = __halves2bfloat162(l0, l1);
                    *(uint32_t*)(Yhi + (size_t)v * 128 + c) = *(uint32_t*)&hp;
                    *(uint32_t*)(Ylo + (size_t)v * 128 + c) = *(uint32_t*)&lp;
                }
            }
        }
    }
}

// ================= edge kernel (C read from global/L1, smem halved) ==========
__global__ __launch_bounds__(256) void edge_kernel(
    const float* __restrict__ node_pos, const float* __restrict__ grid_pos,
    const int* __restrict__ erow, const int* __restrict__ ecol,
    const float* __restrict__ ew1, const float* __restrict__ eb1,
    const float* __restrict__ Cmat, const float* __restrict__ dvec,
    const float* __restrict__ nodeA, float* __restrict__ agg) {
    extern __shared__ float sm[];
    float* uS = sm;                       // 64*128
    float* hS = sm + 8192;                // 64*128
    float* attr = hS + 8192;              // 64*6
    int* rowS = (int*)(attr + 64 * 6);    // 64
    const int tid = threadIdx.x;
    const int ebase = blockIdx.x * 64;

    if (tid < 64) {
        const int e = ebase + tid;
        const int r = erow[e];
        const int c = ecol[e];
        rowS[tid] = r;
        attr[tid * 6 + 0] = node_pos[r * 3 + 0];
        attr[tid * 6 + 1] = node_pos[r * 3 + 1];
        attr[tid * 6 + 2] = node_pos[r * 3 + 2];
        attr[tid * 6 + 3] = grid_pos[c * 3 + 0];
        attr[tid * 6 + 4] = grid_pos[c * 3 + 1];
        attr[tid * 6 + 5] = grid_pos[c * 3 + 2];
    }
    __syncthreads();

    for (int idx = tid; idx < 64 * 128; idx += 256) {
        const int e = idx >> 7, j = idx & 127;
        float s = eb1[j];
        const float* a = attr + e * 6;
#pragma unroll
        for (int i = 0; i < 6; ++i) s += a[i] * ew1[i * 128 + j];
        uS[idx] = silu_f(s);
    }
    __syncthreads();

    const int q = tid & 15, rg = tid >> 4, n0 = q * 4;
    u64 acc[4][4];
#pragma unroll
    for (int i = 0; i < 4; ++i)
#pragma unroll
        for (int j = 0; j < 4; ++j) acc[i][j] = 0ull;
    {
        const float* Ar = uS + rg * 4 * 128;
        const float4* Cr = (const float4*)Cmat;
#pragma unroll 4
        for (int k = 0; k < 128; ++k) {
            float4 b0 = __ldg(&Cr[k * 32 + q]);
            float4 b1 = __ldg(&Cr[k * 32 + 16 + q]);
            u64 B00 = pack2(b0.x, b0.y), B01 = pack2(b0.z, b0.w);
            u64 B10 = pack2(b1.x, b1.y), B11 = pack2(b1.z, b1.w);
#pragma unroll
            for (int i = 0; i < 4; ++i) {
                u64 a = pack2(Ar[i * 128 + k]);
                fma2(acc[i][0], a, B00);
                fma2(acc[i][1], a, B01);
                fma2(acc[i][2], a, B10);
                fma2(acc[i][3], a, B11);
            }
        }
    }

#pragma unroll
    for (int i = 0; i < 4; ++i) {
        const int e = rg * 4 + i;
        const float* na = nodeA + (size_t)rowS[e] * 128;
#pragma unroll
        for (int g = 0; g < 2; ++g) {
            const int c0 = n0 + g * 64;
            float r0, r1, r2, r3;
            unpack2(acc[i][g * 2 + 0], r0, r1);
            unpack2(acc[i][g * 2 + 1], r2, r3);
            float4 o;
            o.x = silu_f(r0 + na[c0 + 0] + dvec[c0 + 0]);
            o.y = silu_f(r1 + na[c0 + 1] + dvec[c0 + 1]);
            o.z = silu_f(r2 + na[c0 + 2] + dvec[c0 + 2]);
            o.w = silu_f(r3 + na[c0 + 3] + dvec[c0 + 3]);
            *(float4*)(hS + e * 128 + c0) = o;
        }
    }
    __syncthreads();

    for (int idx = tid; idx < 8 * 128; idx += 256) {
        const int g = idx >> 7, c = idx & 127;
        float s = 0.f;
#pragma unroll
        for (int j = 0; j < 8; ++j) s += hS[(g * 8 + j) * 128 + c];
        agg[(size_t)(blockIdx.x * 8 + g) * 128 + c] = s * 0.125f;
    }
}

// ================= prep: all 9 conv-weight matrices =================
__global__ __launch_bounds__(256) void prep_all(
    const float* __restrict__ c1, const float* __restrict__ g1,
    const float* __restrict__ c2, const float* __restrict__ g2,
    const float* __restrict__ c5, const float* __restrict__ g5,
    __nv_bfloat16* __restrict__ W1hi, __nv_bfloat16* __restrict__ W1lo,
    __nv_bfloat16* __restrict__ W2hi, __nv_bfloat16* __restrict__ W2lo,
    __nv_bfloat16* __restrict__ W5hi, __nv_bfloat16* __restrict__ W5lo) {
    const int m = blockIdx.y;
    const int blk = m % 3;
    const int kind = m / 3;
    const float* w;
    const float* g;
    __nv_bfloat16 *oh, *ol;
    int T;
    if (kind == 0) {
        T = 27; w = c1 + (size_t)blk * 128 * 128 * 27; g = g1 + blk * 128;
        oh = W1hi + (size_t)blk * 27 * 16384; ol = W1lo + (size_t)blk * 27 * 16384;
    } else if (kind == 1) {
        T = 27; w = c2 + (size_t)blk * 128 * 128 * 27; g = g2 + blk * 128;
        oh = W2hi + (size_t)blk * 27 * 16384; ol = W2lo + (size_t)blk * 27 * 16384;
    } else {
        T = 125; w = c5 + (size_t)blk * 128 * 128 * 125; g = g5 + blk * 128;
        oh = W5hi + (size_t)blk * 125 * 16384; ol = W5lo + (size_t)blk * 125 * 16384;
    }
    const int tidg = blockIdx.x * 256 + threadIdx.x;
    const int o = tidg >> 7, ci = tidg & 127;
    const float s = g[o] * rsqrtf(1.0f + BN_EPS);
    const float* src = w + (size_t)tidg * T;
    for (int t = 0; t < T; ++t) {
        const float val = src[t] * s;
        const __nv_bfloat16 h = __float2bfloat16(val);
        const __nv_bfloat16 l = __float2bfloat16(val - __bfloat162float(h));
        const size_t pos = ((size_t)t * 128 + o) * 128 + ci;
        oh[pos] = h;
        ol[pos] = l;
    }
}

// ================= pool + fc + log_softmax =================
__global__ __launch_bounds__(512) void pool_fc_kernel(
    const float* __restrict__ X, const float* __restrict__ fcw,
    const float* __restrict__ fcb, float* __restrict__ out) {
    __shared__ float part[4][128];
    __shared__ float logits[20];
    const int b = blockIdx.x, tid = threadIdx.x;
    const int c = tid & 127, ch = tid >> 7;
    const float* Xb = X + (size_t)b * 4096 * 128;
    float m0 = -1e30f, m1 = -1e30f, m2 = -1e30f, m3 = -1e30f;
    const int v0 = ch * 1024;
    for (int v = 0; v < 1024; v += 4) {
        m0 = fmaxf(m0, Xb[(size_t)(v0 + v + 0) * 128 + c]);
        m1 = fmaxf(m1, Xb[(size_t)(v0 + v + 1) * 128 + c]);
        m2 = fmaxf(m2, Xb[(size_t)(v0 + v + 2) * 128 + c]);
        m3 = fmaxf(m3, Xb[(size_t)(v0 + v + 3) * 128 + c]);
    }
    part[ch][c] = fmaxf(fmaxf(m0, m1), fmaxf(m2, m3));
    __syncthreads();
    if (tid < 128) {
        part[0][tid] = fmaxf(fmaxf(part[0][tid], part[1][tid]),
                             fmaxf(part[2][tid], part[3][tid]));
    }
    __syncthreads();
    if (tid < 20) {
        float s = fcb[tid];
        for (int k = 0; k < 128; ++k) s += part[0][k] * fcw[k * 20 + tid];
        logits[tid] = s;
    }
    __syncthreads();
    if (tid == 0) {
        float mx = logits[0];
        for (int j = 1; j < 20; ++j) mx = fmaxf(mx, logits[j]);
        float se = 0.f;
        for (int j = 0; j < 20; ++j) se += expf(logits[j] - mx);
        const float lse = logf(se) + mx;
        for (int j = 0; j < 20; ++j) out[b * 20 + j] = logits[j] - lse;
    }
}

// ================= host launch =================
extern "C" void kernel_launch(void* const* d_in, const int* in_sizes, int n_in,
                              void* d_out, int out_size) {
    const float* node_embedding = (const float*)d_in[0];
    const float* node_pos = (const float*)d_in[1];
    const float* grid_pos = (const float*)d_in[2];
    const int* edge_row = (const int*)d_in[3];
    const int* edge_col = (const int*)d_in[4];
    const float* edge_w1 = (const float*)d_in[5];
    const float* edge_b1 = (const float*)d_in[6];
    const float* edge_w2 = (const float*)d_in[7];
    const float* edge_b2 = (const float*)d_in[8];
    const float* msg_w1 = (const float*)d_in[9];
    const float* msg_b1 = (const float*)d_in[10];
    const float* msg_w2 = (const float*)d_in[11];
    const float* msg_b2 = (const float*)d_in[12];
    const float* upd_w1 = (const float*)d_in[13];
    const float* upd_b1 = (const float*)d_in[14];
    const float* upd_w2 = (const float*)d_in[15];
    const float* upd_b2 = (const float*)d_in[16];
    const float* in_gamma = (const float*)d_in[17];
    const float* in_beta = (const float*)d_in[18];
    const float* blk_conv1 = (const float*)d_in[19];
    const float* blk_bn1_g = (const float*)d_in[20];
    const float* blk_bn1_b = (const float*)d_in[21];
    const float* blk_conv2 = (const float*)d_in[22];
    const float* blk_bn2_g = (const float*)d_in[23];
    const float* blk_bn2_b = (const float*)d_in[24];
    const float* blk_conv5 = (const float*)d_in[25];
    const float* blk_bns_g = (const float*)d_in[26];
    const float* blk_bns_b = (const float*)d_in[27];
    const float* fc_w = (const float*)d_in[28];
    const float* fc_b = (const float*)d_in[29];
    float* out = (float*)d_out;

    float *bufA, *bufB, *bufD, *nodeA, *Cm, *dv;
    __nv_bfloat16 *xhiA, *xloA, *xhiB, *xloB, *ahi, *alo;
    __nv_bfloat16 *W1hi, *W1lo, *W2hi, *W2lo, *W5hi, *W5lo;
    cudaGetSymbolAddress((void**)&bufA, g_bufA);
    cudaGetSymbolAddress((void**)&bufB, g_bufB);
    cudaGetSymbolAddress((void**)&bufD, g_bufD);
    cudaGetSymbolAddress((void**)&nodeA, g_nodeA);
    cudaGetSymbolAddress((void**)&Cm, g_C);
    cudaGetSymbolAddress((void**)&dv, g_d);
    cudaGetSymbolAddress((void**)&xhiA, g_xhiA);
    cudaGetSymbolAddress((void**)&xloA, g_xloA);
    cudaGetSymbolAddress((void**)&xhiB, g_xhiB);
    cudaGetSymbolAddress((void**)&xloB, g_xloB);
    cudaGetSymbolAddress((void**)&ahi, g_ahi);
    cudaGetSymbolAddress((void**)&alo, g_alo);
    cudaGetSymbolAddress((void**)&W1hi, g_W1hi);
    cudaGetSymbolAddress((void**)&W1lo, g_W1lo);
    cudaGetSymbolAddress((void**)&W2hi, g_W2hi);
    cudaGetSymbolAddress((void**)&W2lo, g_W2lo);
    cudaGetSymbolAddress((void**)&W5hi, g_W5hi);
    cudaGetSymbolAddress((void**)&W5lo, g_W5lo);

    const int SMEM_GEMM = (64 * 128 + 128 * 128) * 4;
    const int SMEM_EDGE = (8192 + 8192 + 384) * 4 + 64 * 4;

    cudaFuncSetAttribute(combo_gemm, cudaFuncAttributeMaxDynamicSharedMemorySize, SMEM_GEMM);
    cudaFuncSetAttribute(fused_mlp, cudaFuncAttributeMaxDynamicSharedMemorySize, SMEM_GEMM);
    cudaFuncSetAttribute(edge_kernel, cudaFuncAttributeMaxDynamicSharedMemorySize, SMEM_EDGE);
    cudaFuncSetAttribute(conv_mma<3, E_RELU_SPLIT>, cudaFuncAttributeMaxDynamicSharedMemorySize, C_SMEM);
    cudaFuncSetAttribute(conv_mma<3, E_ADDRELU_SPLIT_F32>, cudaFuncAttributeMaxDynamicSharedMemorySize, C_SMEM);
    cudaFuncSetAttribute(conv_mma<5, E_F32>, cudaFuncAttributeMaxDynamicSharedMemorySize, C_SMEM);

    // 0: Cm + nodeA + dvec
    combo_gemm<<<35, 256, SMEM_GEMM>>>(node_embedding, edge_w2, msg_w1, edge_b2,
                                       msg_b1, Cm, nodeA, dv);
    // 1: conv weight prep
    prep_all<<<dim3(64, 9), 256>>>(blk_conv1, blk_bn1_g, blk_conv2, blk_bn2_g,
                                   blk_conv5, blk_bns_g, W1hi, W1lo, W2hi, W2lo,
                                   W5hi, W5lo);
    // 2: edges -> agg
    edge_kernel<<<1024, 256, SMEM_EDGE>>>(node_pos, grid_pos, edge_row, edge_col,
                                          edge_w1, edge_b1, Cm, dv, nodeA, bufA);
    // 3: fused grid MLP chain -> BN -> hi/lo split
    fused_mlp<<<128, 256, SMEM_GEMM>>>(bufA, msg_w2, msg_b2, upd_w1, upd_b1,
                                       upd_w2, upd_b2, in_gamma, in_beta, xhiA, xloA);

    // 4..12: 3 residual blocks
    __nv_bfloat16 *xh = xhiA, *xl = xloA, *nh = xhiB, *nl = xloB;
    for (int i = 0; i < 3; ++i) {
        conv_mma<5, E_F32><<<128, 256, C_SMEM>>>(
            xh, xl, W5hi + (size_t)i * 125 * 16384, W5lo + (size_t)i * 125 * 16384,
            blk_bns_b + i * 128, nullptr, bufB, nullptr, nullptr);
        conv_mma<3, E_RELU_SPLIT><<<128, 256, C_SMEM>>>(
            xh, xl, W1hi + (size_t)i * 27 * 16384, W1lo + (size_t)i * 27 * 16384,
            blk_bn1_b + i * 128, nullptr, nullptr, ahi, alo);
        conv_mma<3, E_ADDRELU_SPLIT_F32><<<128, 256, C_SMEM>>>(
            ahi, alo, W2hi + (size_t)i * 27 * 16384, W2lo + (size_t)i * 27 * 16384,
            blk_bn2_b + i * 128, bufB, bufD, nh, nl);
        __nv_bfloat16* t;
        t = xh; xh = nh; nh = t;
        t = xl; xl = nl; nl = t;
    }

    // 13: pool + fc + log_softmax
    pool_fc_kernel<<<2, 512>>>(bufD, fc_w, fc_b, out);
    (void)in_sizes; (void)n_in; (void)out_size;
}

// round 7
// speedup vs baseline: 2.6882x; 1.0016x over previous
#include <cuda_runtime.h>
#include <cuda_bf16.h>
#include <math.h>
#include <stdint.h>

#define BN_EPS 1e-5f

typedef unsigned long long u64;

// ================= helpers =================
__device__ __forceinline__ uint32_t smem_u32_of(const void* p) {
    uint32_t a;
    asm("{ .reg .u64 t; cvta.to.shared.u64 t, %1; cvt.u32.u64 %0, t; }" : "=r"(a) : "l"(p));
    return a;
}

__device__ __forceinline__ void ldsm4(uint32_t* r, uint32_t addr) {
    asm volatile("ldmatrix.sync.aligned.m8n8.x4.shared.b16 {%0,%1,%2,%3}, [%4];"
                 : "=r"(r[0]), "=r"(r[1]), "=r"(r[2]), "=r"(r[3]) : "r"(addr));
}

__device__ __forceinline__ void mma16816(float* c, const uint32_t* a, uint32_t b0, uint32_t b1) {
    asm volatile(
        "mma.sync.aligned.m16n8k16.row.col.f32.bf16.bf16.f32 "
        "{%0,%1,%2,%3}, {%4,%5,%6,%7}, {%8,%9}, {%0,%1,%2,%3};"
        : "+f"(c[0]), "+f"(c[1]), "+f"(c[2]), "+f"(c[3])
        : "r"(a[0]), "r"(a[1]), "r"(a[2]), "r"(a[3]), "r"(b0), "r"(b1));
}

#define CP_ASYNC16_CG(dst, src, sz) \
    asm volatile("cp.async.cg.shared.global [%0], [%1], 16, %2;" :: \
        "r"(dst), "l"(src), "r"(sz) : "memory")
#define CP_ASYNC16_CA(dst, src, sz) \
    asm volatile("cp.async.ca.shared.global [%0], [%1], 16, %2;" :: \
        "r"(dst), "l"(src), "r"(sz) : "memory")
#define CP_COMMIT() asm volatile("cp.async.commit_group;" ::: "memory")
#define CP_WAIT(n) asm volatile("cp.async.wait_group %0;" :: "n"(n) : "memory")

// producer-consumer named barriers (256 arrivers + 256 syncers = 512)
#define NBAR_SYNC(id) \
    asm volatile("bar.sync %0, 512;" :: "r"(id) : "memory")
#define NBAR_ARRIVE(id) \
    asm volatile("bar.arrive %0, 512;" :: "r"(id) : "memory")

// ================= packed f32x2 (SIMT GEMM path) =================
__device__ __forceinline__ u64 pack2(float x) {
    u64 r; asm("mov.b64 %0, {%1, %1};" : "=l"(r) : "f"(x)); return r;
}
__device__ __forceinline__ u64 pack2(float x, float y) {
    u64 r; asm("mov.b64 %0, {%1, %2};" : "=l"(r) : "f"(x), "f"(y)); return r;
}
__device__ __forceinline__ void unpack2(u64 v, float& x, float& y) {
    asm("mov.b64 {%0, %1}, %2;" : "=f"(x), "=f"(y) : "l"(v));
}
__device__ __forceinline__ void fma2(u64& d, u64 a, u64 b) {
    asm("fma.rn.f32x2 %0, %1, %2, %0;" : "+l"(d) : "l"(a), "l"(b));
}
__device__ __forceinline__ float silu_f(float x) { return x / (1.0f + __expf(-x)); }

// ================= static scratch =================
__device__ float g_bufA[8192 * 128];
__device__ float g_bufB[8192 * 128];
__device__ float g_bufD[8192 * 128];
__device__ float g_nodeA[2048 * 128];
__device__ float g_C[128 * 128];
__device__ float g_d[128];
__device__ __nv_bfloat16 g_xhiA[8192 * 128];
__device__ __nv_bfloat16 g_xloA[8192 * 128];
__device__ __nv_bfloat16 g_xhiB[8192 * 128];
__device__ __nv_bfloat16 g_xloB[8192 * 128];
__device__ __nv_bfloat16 g_ahi[8192 * 128];
__device__ __nv_bfloat16 g_alo[8192 * 128];
__device__ __nv_bfloat16 g_W1hi[3 * 27 * 128 * 128];
__device__ __nv_bfloat16 g_W1lo[3 * 27 * 128 * 128];
__device__ __nv_bfloat16 g_W2hi[3 * 27 * 128 * 128];
__device__ __nv_bfloat16 g_W2lo[3 * 27 * 128 * 128];
__device__ __nv_bfloat16 g_W5hi[3 * 125 * 128 * 128];
__device__ __nv_bfloat16 g_W5lo[3 * 125 * 128 * 128];

// ================= SIMT 64x128x128 MMA core (smem B) =================
__device__ __forceinline__ void mma_64x128x128(const float* __restrict__ As,
                                               const float* __restrict__ Bs,
                                               u64 acc[4][4], int tid) {
    const int q = tid & 15;
    const int rg = tid >> 4;
    const float* Ar = As + rg * 4 * 128;
    const int n0 = q * 4;
#pragma unroll 4
    for (int k = 0; k < 128; ++k) {
        float4 b0 = *(const float4*)(Bs + k * 128 + n0);
        float4 b1 = *(const float4*)(Bs + k * 128 + n0 + 64);
        u64 B00 = pack2(b0.x, b0.y), B01 = pack2(b0.z, b0.w);
        u64 B10 = pack2(b1.x, b1.y), B11 = pack2(b1.z, b1.w);
#pragma unroll
        for (int i = 0; i < 4; ++i) {
            u64 a = pack2(Ar[i * 128 + k]);
            fma2(acc[i][0], a, B00);
            fma2(acc[i][1], a, B01);
            fma2(acc[i][2], a, B10);
            fma2(acc[i][3], a, B11);
        }
    }
}

// ====== combo: Cm (bx 0-1) + nodeA (2-33) + dvec (34) + conv-weight prep (35-610) ====
__global__ __launch_bounds__(256) void combo_gemm(
    const float* __restrict__ node_embedding, const float* __restrict__ edge_w2,
    const float* __restrict__ msg_w1, const float* __restrict__ eb2,
    const float* __restrict__ mb1, float* __restrict__ Cm,
    float* __restrict__ nodeA, float* __restrict__ dvec,
    const float* __restrict__ c1, const float* __restrict__ g1,
    const float* __restrict__ c2, const float* __restrict__ g2,
    const float* __restrict__ c5, const float* __restrict__ g5,
    __nv_bfloat16* __restrict__ W1hi, __nv_bfloat16* __restrict__ W1lo,
    __nv_bfloat16* __restrict__ W2hi, __nv_bfloat16* __restrict__ W2lo,
    __nv_bfloat16* __restrict__ W5hi, __nv_bfloat16* __restrict__ W5lo) {
    extern __shared__ float sm[];
    const int tid = threadIdx.x;

    if (blockIdx.x >= 35) {
        // ---- conv weight prep: 576 blocks (9 matrices x 64) ----
        const int pb = blockIdx.x - 35;
        const int m = pb >> 6;          // 0..8
        const int inner = pb & 63;      // 0..63
        const int blk = m % 3;
        const int kind = m / 3;
        const float* w;
        const float* g;
        __nv_bfloat16 *oh, *ol;
        int T;
        if (kind == 0) {
            T = 27; w = c1 + (size_t)blk * 128 * 128 * 27; g = g1 + blk * 128;
            oh = W1hi + (size_t)blk * 27 * 16384; ol = W1lo + (size_t)blk * 27 * 16384;
        } else if (kind == 1) {
            T = 27; w = c2 + (size_t)blk * 128 * 128 * 27; g = g2 + blk * 128;
            oh = W2hi + (size_t)blk * 27 * 16384; ol = W2lo + (size_t)blk * 27 * 16384;
        } else {
            T = 125; w = c5 + (size_t)blk * 128 * 128 * 125; g = g5 + blk * 128;
            oh = W5hi + (size_t)blk * 125 * 16384; ol = W5lo + (size_t)blk * 125 * 16384;
        }
        const int tidg = inner * 256 + tid;
        const int o = tidg >> 7, ci = tidg & 127;
        const float s = g[o] * rsqrtf(1.0f + BN_EPS);
        const float* src = w + (size_t)tidg * T;
        for (int t = 0; t < T; ++t) {
            const float val = src[t] * s;
            const __nv_bfloat16 h = __float2bfloat16(val);
            const __nv_bfloat16 l = __float2bfloat16(val - __bfloat162float(h));
            const size_t pos = ((size_t)t * 128 + o) * 128 + ci;
            oh[pos] = h;
            ol[pos] = l;
        }
        return;
    }

    if (blockIdx.x == 34) {
        if (tid < 128) {
            const int n = tid;
            float s = mb1[n];
            for (int k = 0; k < 128; ++k) s += eb2[k] * msg_w1[(128 + k) * 128 + n];
            dvec[n] = s;
        }
        return;
    }

    float* As = sm;
    float* Bs = sm + 64 * 128;
    const float* A;
    const float* W;
    float* Y;
    int row0;
    if (blockIdx.x < 2) {
        A = edge_w2; W = msg_w1 + 128 * 128; Y = Cm; row0 = blockIdx.x * 64;
    } else {
        A = node_embedding; W = msg_w1; Y = nodeA; row0 = (blockIdx.x - 2) * 64;
    }
    const float4* A4 = (const float4*)(A + (size_t)row0 * 128);
    float4* Ad = (float4*)As;
#pragma unroll
    for (int j = 0; j < 8; ++j) Ad[tid + j * 256] = A4[tid + j * 256];
    const float4* W4 = (const float4*)W;
    float4* Bd = (float4*)Bs;
#pragma unroll
    for (int j = 0; j < 16; ++j) Bd[tid + j * 256] = W4[tid + j * 256];
    __syncthreads();

    u64 acc[4][4];
#pragma unroll
    for (int i = 0; i < 4; ++i)
#pragma unroll
        for (int j = 0; j < 4; ++j) acc[i][j] = 0ull;
    mma_64x128x128(As, Bs, acc, tid);

    const int q = tid & 15, rg = tid >> 4, n0 = q * 4;
#pragma unroll
    for (int i = 0; i < 4; ++i) {
        const int v = row0 + rg * 4 + i;
#pragma unroll
        for (int g = 0; g < 2; ++g) {
            const int c0 = n0 + g * 64;
            float r0, r1, r2, r3;
            unpack2(acc[i][g * 2 + 0], r0, r1);
            unpack2(acc[i][g * 2 + 1], r2, r3);
            *(float4*)(Y + (size_t)v * 128 + c0) = make_float4(r0, r1, r2, r3);
        }
    }
}

// ================= fused MLP =================
__global__ __launch_bounds__(256) void fused_mlp(
    const float* __restrict__ agg,
    const float* __restrict__ msg_w2, const float* __restrict__ msg_b2,
    const float* __restrict__ upd_w1, const float* __restrict__ upd_b1,
    const float* __restrict__ upd_w2, const float* __restrict__ upd_b2,
    const float* __restrict__ gamma, const float* __restrict__ beta,
    __nv_bfloat16* __restrict__ Yhi, __nv_bfloat16* __restrict__ Ylo) {
    extern __shared__ float sm[];
    float* As = sm;
    float* Bs = sm + 64 * 128;
    const int tid = threadIdx.x;
    const int row0 = blockIdx.x * 64;
    const int q = tid & 15, rg = tid >> 4, n0 = q * 4;

    {
        const float4* A4 = (const float4*)(agg + (size_t)row0 * 128);
        float4* Ad = (float4*)As;
#pragma unroll
        for (int j = 0; j < 8; ++j) Ad[tid + j * 256] = A4[tid + j * 256];
    }

    const float* Ws[3] = {msg_w2, upd_w1, upd_w2};
    const float* Bv[3] = {msg_b2, upd_b1, upd_b2};

#pragma unroll
    for (int s = 0; s < 3; ++s) {
        const float4* W4 = (const float4*)Ws[s];
        float4* Bd = (float4*)Bs;
#pragma unroll
        for (int j = 0; j < 16; ++j) Bd[tid + j * 256] = W4[tid + j * 256];
        __syncthreads();

        u64 acc[4][4];
#pragma unroll
        for (int i = 0; i < 4; ++i)
#pragma unroll
            for (int j = 0; j < 4; ++j) acc[i][j] = 0ull;
        mma_64x128x128(As, Bs, acc, tid);
        __syncthreads();

        const float* bias = Bv[s];
#pragma unroll
        for (int i = 0; i < 4; ++i) {
            const int r = rg * 4 + i;
#pragma unroll
            for (int g = 0; g < 2; ++g) {
                const int c0 = n0 + g * 64;
                float o0, o1, o2, o3;
                unpack2(acc[i][g * 2 + 0], o0, o1);
                unpack2(acc[i][g * 2 + 1], o2, o3);
                o0 += bias[c0 + 0]; o1 += bias[c0 + 1];
                o2 += bias[c0 + 2]; o3 += bias[c0 + 3];
                if (s == 1) {
                    o0 = silu_f(o0); o1 = silu_f(o1);
                    o2 = silu_f(o2); o3 = silu_f(o3);
                }
                if (s < 2) {
                    *(float4*)(As + r * 128 + c0) = make_float4(o0, o1, o2, o3);
                } else {
                    const float rs = rsqrtf(1.0f + BN_EPS);
                    o0 = o0 * (gamma[c0 + 0] * rs) + beta[c0 + 0];
                    o1 = o1 * (gamma[c0 + 1] * rs) + beta[c0 + 1];
                    o2 = o2 * (gamma[c0 + 2] * rs) + beta[c0 + 2];
                    o3 = o3 * (gamma[c0 + 3] * rs) + beta[c0 + 3];
                    __nv_bfloat16 h0 = __float2bfloat16(o0), h1 = __float2bfloat16(o1);
                    __nv_bfloat16 h2 = __float2bfloat16(o2), h3 = __float2bfloat16(o3);
                    __nv_bfloat16 l0 = __float2bfloat16(o0 - __bfloat162float(h0));
                    __nv_bfloat16 l1 = __float2bfloat16(o1 - __bfloat162float(h1));
                    __nv_bfloat16 l2 = __float2bfloat16(o2 - __bfloat162float(h2));
                    __nv_bfloat16 l3 = __float2bfloat16(o3 - __bfloat162float(h3));
                    __nv_bfloat162 hp0 = __halves2bfloat162(h0, h1);
                    __nv_bfloat162 hp1 = __halves2bfloat162(h2, h3);
                    __nv_bfloat162 lp0 = __halves2bfloat162(l0, l1);
                    __nv_bfloat162 lp1 = __halves2bfloat162(l2, l3);
                    const int v = row0 + r;
                    *(uint2*)(Yhi + (size_t)v * 128 + c0) =
                        make_uint2(*(uint32_t*)&hp0, *(uint32_t*)&hp1);
                    *(uint2*)(Ylo + (size_t)v * 128 + c0) =
                        make_uint2(*(uint32_t*)&lp0, *(uint32_t*)&lp1);
                }
            }
        }
        __syncthreads();
    }
}

// ================= tensor-core conv via mma.sync (3-term bf16 split) =================
#define E_RELU_SPLIT 0
#define E_F32 1
#define E_ADDRELU_SPLIT_F32 2

#define CSTG 98304
#define C_AHI 0
#define C_ALO 16384
#define C_BHI 32768
#define C_BLO 65536
#define C_BIAS (2 * CSTG)
#define C_SMEM (C_BIAS + 512)

template <int KS, int EPI>
__global__ __launch_bounds__(256, 1) void conv_mma(
    const __nv_bfloat16* __restrict__ Xhi, const __nv_bfloat16* __restrict__ Xlo,
    const __nv_bfloat16* __restrict__ Whi, const __nv_bfloat16* __restrict__ Wlo,
    const float* __restrict__ bias, const float* __restrict__ addb,
    float* __restrict__ Yf32, __nv_bfloat16* __restrict__ Yhi,
    __nv_bfloat16* __restrict__ Ylo) {
    extern __shared__ char smc[];
    const uint32_t sb = smem_u32_of(smc);
    const int tid = threadIdx.x;
    const int lane = tid & 31, wid = tid >> 5;
    constexpr int P = KS / 2;
    constexpr int TAPS = KS * KS * KS;

    const int vbase = blockIdx.x * 64;
    const int y0 = (vbase >> 4) & 15;
    const int z = (vbase >> 8) & 15;
    const int bb = vbase >> 12;

    if (tid < 128) ((float*)(smc + C_BIAS))[tid] = bias[tid];

    auto issue = [&](int tap, int stage) {
        const int dz = tap / (KS * KS);
        const int rem = tap - dz * KS * KS;
        const int dy = rem / KS, dx = rem - dy * KS;
        const int iz = z + dz - P;
        const uint32_t stb = sb + stage * CSTG;
        const bool zok = (iz >= 0) && (iz < 16);
#pragma unroll
        for (int i = 0; i < 4; ++i) {
            const int ga = tid + i * 256;
            const int r = ga >> 4, g = ga & 15;
            const int iy = y0 + (r >> 4) + dy - P;
            const int ix = (r & 15) + dx - P;
            const bool ok = zok && (iy >= 0) && (iy < 16) && (ix >= 0) && (ix < 16);
            const int vox = ok ? (((bb * 16 + iz) * 16 + iy) * 16 + ix) : 0;
            const uint32_t srcsz = ok ? 16u : 0u;
            const size_t goff = (size_t)vox * 128 + g * 8;
            const uint32_t rel = r * 256 + (((uint32_t)(((g ^ r) & 7) | (g & 8))) << 4);
            CP_ASYNC16_CA(stb + C_AHI + rel, Xhi + goff, srcsz);
            CP_ASYNC16_CA(stb + C_ALO + rel, Xlo + goff, srcsz);
        }
#pragma unroll
        for (int i = 0; i < 8; ++i) {
            const int gb = tid + i * 256;
            const int r = gb >> 4, g = gb & 15;
            const size_t goff = ((size_t)tap * 128 + r) * 128 + g * 8;
            const uint32_t rel = r * 256 + (((uint32_t)(((g ^ r) & 7) | (g & 8))) << 4);
            CP_ASYNC16_CG(stb + C_BHI + rel, Whi + goff, 16u);
            CP_ASYNC16_CG(stb + C_BLO + rel, Wlo + goff, 16u);
        }
        CP_COMMIT();
    };

    float acc[2][4][4];
#pragma unroll
    for (int i = 0; i < 2; ++i)
#pragma unroll
        for (int j = 0; j < 4; ++j)
#pragma unroll
            for (int k = 0; k < 4; ++k) acc[i][j][k] = 0.f;

    const int warp_m = wid >> 2, warp_n = wid & 3;
    uint32_t aRel[2], aXor[2];
#pragma unroll
    for (int ma = 0; ma < 2; ++ma) {
        const int row = warp_m * 32 + ma * 16 + (lane & 15);
        aRel[ma] = row * 256;
        aXor[ma] = row & 7;
    }
    uint32_t bRel[2], bXor[2];
#pragma unroll
    for (int nt = 0; nt < 2; ++nt) {
        const int row = warp_n * 32 + nt * 16 + ((lane >> 4) << 3) + (lane & 7);
        bRel[nt] = row * 256;
        bXor[nt] = row & 7;
    }
    const uint32_t gAsel = lane >> 4;
    const uint32_t gBsel = (lane >> 3) & 1;

    issue(0, 0);
    for (int tap = 0; tap < TAPS; ++tap) {
        if (tap + 1 < TAPS) {
            // stage (tap+1)&1 is free once all warps posted arrive during tap-1.
            if (tap > 0) NBAR_SYNC(1 + ((tap + 1) & 1));
            issue(tap + 1, (tap + 1) & 1);
            CP_WAIT(1);   // own copies for tap done (tap+1 still in flight)
        } else {
            CP_WAIT(0);
        }
        __syncthreads();  // all threads' copies for tap visible

        const uint32_t stb = sb + (tap & 1) * CSTG;
#pragma unroll
        for (int ks = 0; ks < 8; ++ks) {
            uint32_t aH[2][4], aL[2][4], bH[2][4], bL[2][4];
            const uint32_t gA = ks * 2 + gAsel;
            const uint32_t gB = ks * 2 + gBsel;
#pragma unroll
            for (int ma = 0; ma < 2; ++ma) {
                const uint32_t sw = (((gA ^ aXor[ma]) & 7) | (gA & 8)) << 4;
                ldsm4(aH[ma], stb + C_AHI + aRel[ma] + sw);
                ldsm4(aL[ma], stb + C_ALO + aRel[ma] + sw);
            }
#pragma unroll
            for (int nt = 0; nt < 2; ++nt) {
                const uint32_t sw = (((gB ^ bXor[nt]) & 7) | (gB & 8)) << 4;
                ldsm4(bH[nt], stb + C_BHI + bRel[nt] + sw);
                ldsm4(bL[nt], stb + C_BLO + bRel[nt] + sw);
            }
            // after the warp's LAST ldsm of this stage, signal FREE (non-blocking)
            if (ks == 7) NBAR_ARRIVE(1 + (tap & 1));
#pragma unroll
            for (int ma = 0; ma < 2; ++ma)
#pragma unroll
                for (int nb = 0; nb < 4; ++nb) {
                    const uint32_t b0h = bH[nb >> 1][(nb & 1) * 2];
                    const uint32_t b1h = bH[nb >> 1][(nb & 1) * 2 + 1];
                    const uint32_t b0l = bL[nb >> 1][(nb & 1) * 2];
                    const uint32_t b1l = bL[nb >> 1][(nb & 1) * 2 + 1];
                    mma16816(acc[ma][nb], aH[ma], b0h, b1h);
                    mma16816(acc[ma][nb], aH[ma], b0l, b1l);
                    mma16816(acc[ma][nb], aL[ma], b0h, b1h);
                }
        }
    }

    // ---- epilogue ----
    const float* biasS = (const float*)(smc + C_BIAS);
#pragma unroll
    for (int ma = 0; ma < 2; ++ma) {
        const int r0 = vbase + warp_m * 32 + ma * 16 + (lane >> 2);
#pragma unroll
        for (int half = 0; half < 2; ++half) {
            const int v = r0 + half * 8;
#pragma unroll
            for (int nb = 0; nb < 4; ++nb) {
                const int c = warp_n * 32 + nb * 8 + (lane & 3) * 2;
                float o0 = acc[ma][nb][half * 2 + 0] + biasS[c];
                float o1 = acc[ma][nb][half * 2 + 1] + biasS[c + 1];
                if (EPI == E_ADDRELU_SPLIT_F32) {
                    const float2 a = *(const float2*)(addb + (size_t)v * 128 + c);
                    o0 += a.x;
                    o1 += a.y;
                }
                if (EPI != E_F32) {
                    o0 = fmaxf(o0, 0.f);
                    o1 = fmaxf(o1, 0.f);
                }
                if (EPI != E_RELU_SPLIT)
                    *(float2*)(Yf32 + (size_t)v * 128 + c) = make_float2(o0, o1);
                if (EPI != E_F32) {
                    __nv_bfloat16 h0 = __float2bfloat16(o0);
                    __nv_bfloat16 h1 = __float2bfloat16(o1);
                    __nv_bfloat16 l0 = __float2bfloat16(o0 - __bfloat162float(h0));
                    __nv_bfloat16 l1 = __float2bfloat16(o1 - __bfloat162float(h1));
                    __nv_bfloat162 hp = __halves2bfloat162(h0, h1);
                    __nv_bfloat162 lp = __halves2bfloat162(l0, l1);
                    *(uint32_t*)(Yhi + (size_t)v * 128 + c) = *(uint32_t*)&hp;
                    *(uint32_t*)(Ylo + (size_t)v * 128 + c) = *(uint32_t*)&lp;
                }
            }
        }
    }
}

// ================= edge kernel =================
__global__ __launch_bounds__(256) void edge_kernel(
    const float* __restrict__ node_pos, const float* __restrict__ grid_pos,
    const int* __restrict__ erow, const int* __restrict__ ecol,
    const float* __restrict__ ew1, const float* __restrict__ eb1,
    const float* __restrict__ Cmat, const float* __restrict__ dvec,
    const float* __restrict__ nodeA, float* __restrict__ agg) {
    extern __shared__ float sm[];
    float* uS = sm;
    float* hS = sm + 8192;
    float* attr = hS + 8192;
    int* rowS = (int*)(attr + 64 * 6);
    const int tid = threadIdx.x;
    const int ebase = blockIdx.x * 64;

    if (tid < 64) {
        const int e = ebase + tid;
        const int r = erow[e];
        const int c = ecol[e];
        rowS[tid] = r;
        attr[tid * 6 + 0] = node_pos[r * 3 + 0];
        attr[tid * 6 + 1] = node_pos[r * 3 + 1];
        attr[tid * 6 + 2] = node_pos[r * 3 + 2];
        attr[tid * 6 + 3] = grid_pos[c * 3 + 0];
        attr[tid * 6 + 4] = grid_pos[c * 3 + 1];
        attr[tid * 6 + 5] = grid_pos[c * 3 + 2];
    }
    __syncthreads();

    for (int idx = tid; idx < 64 * 128; idx += 256) {
        const int e = idx >> 7, j = idx & 127;
        float s = eb1[j];
        const float* a = attr + e * 6;
#pragma unroll
        for (int i = 0; i < 6; ++i) s += a[i] * ew1[i * 128 + j];
        uS[idx] = silu_f(s);
    }
    __syncthreads();

    const int q = tid & 15, rg = tid >> 4, n0 = q * 4;
    u64 acc[4][4];
#pragma unroll
    for (int i = 0; i < 4; ++i)
#pragma unroll
        for (int j = 0; j < 4; ++j) acc[i][j] = 0ull;
    {
        const float* Ar = uS + rg * 4 * 128;
        const float4* Cr = (const float4*)Cmat;
#pragma unroll 4
        for (int k = 0; k < 128; ++k) {
            float4 b0 = __ldg(&Cr[k * 32 + q]);
            float4 b1 = __ldg(&Cr[k * 32 + 16 + q]);
            u64 B00 = pack2(b0.x, b0.y), B01 = pack2(b0.z, b0.w);
            u64 B10 = pack2(b1.x, b1.y), B11 = pack2(b1.z, b1.w);
#pragma unroll
            for (int i = 0; i < 4; ++i) {
                u64 a = pack2(Ar[i * 128 + k]);
                fma2(acc[i][0], a, B00);
                fma2(acc[i][1], a, B01);
                fma2(acc[i][2], a, B10);
                fma2(acc[i][3], a, B11);
            }
        }
    }

#pragma unroll
    for (int i = 0; i < 4; ++i) {
        const int e = rg * 4 + i;
        const float* na = nodeA + (size_t)rowS[e] * 128;
#pragma unroll
        for (int g = 0; g < 2; ++g) {
            const int c0 = n0 + g * 64;
            float r0, r1, r2, r3;
            unpack2(acc[i][g * 2 + 0], r0, r1);
            unpack2(acc[i][g * 2 + 1], r2, r3);
            float4 o;
            o.x = silu_f(r0 + na[c0 + 0] + dvec[c0 + 0]);
            o.y = silu_f(r1 + na[c0 + 1] + dvec[c0 + 1]);
            o.z = silu_f(r2 + na[c0 + 2] + dvec[c0 + 2]);
            o.w = silu_f(r3 + na[c0 + 3] + dvec[c0 + 3]);
            *(float4*)(hS + e * 128 + c0) = o;
        }
    }
    __syncthreads();

    for (int idx = tid; idx < 8 * 128; idx += 256) {
        const int g = idx >> 7, c = idx & 127;
        float s = 0.f;
#pragma unroll
        for (int j = 0; j < 8; ++j) s += hS[(g * 8 + j) * 128 + c];
        agg[(size_t)(blockIdx.x * 8 + g) * 128 + c] = s * 0.125f;
    }
}

// ================= pool + fc + log_softmax =================
__global__ __launch_bounds__(512) void pool_fc_kernel(
    const float* __restrict__ X, const float* __restrict__ fcw,
    const float* __restrict__ fcb, float* __restrict__ out) {
    __shared__ float part[4][128];
    __shared__ float logits[20];
    const int b = blockIdx.x, tid = threadIdx.x;
    const int c = tid & 127, ch = tid >> 7;
    const float* Xb = X + (size_t)b * 4096 * 128;
    float m0 = -1e30f, m1 = -1e30f, m2 = -1e30f, m3 = -1e30f;
    const int v0 = ch * 1024;
    for (int v = 0; v < 1024; v += 4) {
        m0 = fmaxf(m0, Xb[(size_t)(v0 + v + 0) * 128 + c]);
        m1 = fmaxf(m1, Xb[(size_t)(v0 + v + 1) * 128 + c]);
        m2 = fmaxf(m2, Xb[(size_t)(v0 + v + 2) * 128 + c]);
        m3 = fmaxf(m3, Xb[(size_t)(v0 + v + 3) * 128 + c]);
    }
    part[ch][c] = fmaxf(fmaxf(m0, m1), fmaxf(m2, m3));
    __syncthreads();
    if (tid < 128) {
        part[0][tid] = fmaxf(fmaxf(part[0][tid], part[1][tid]),
                             fmaxf(part[2][tid], part[3][tid]));
    }
    __syncthreads();
    if (tid < 20) {
        float s = fcb[tid];
        for (int k = 0; k < 128; ++k) s += part[0][k] * fcw[k * 20 + tid];
        logits[tid] = s;
    }
    __syncthreads();
    if (tid == 0) {
        float mx = logits[0];
        for (int j = 1; j < 20; ++j) mx = fmaxf(mx, logits[j]);
        float se = 0.f;
        for (int j = 0; j < 20; ++j) se += expf(logits[j] - mx);
        const float lse = logf(se) + mx;
        for (int j = 0; j < 20; ++j) out[b * 20 + j] = logits[j] - lse;
    }
}

// ================= host launch =================
extern "C" void kernel_launch(void* const* d_in, const int* in_sizes, int n_in,
                              void* d_out, int out_size) {
    const float* node_embedding = (const float*)d_in[0];
    const float* node_pos = (const float*)d_in[1];
    const float* grid_pos = (const float*)d_in[2];
    const int* edge_row = (const int*)d_in[3];
    const int* edge_col = (const int*)d_in[4];
    const float* edge_w1 = (const float*)d_in[5];
    const float* edge_b1 = (const float*)d_in[6];
    const float* edge_w2 = (const float*)d_in[7];
    const float* edge_b2 = (const float*)d_in[8];
    const float* msg_w1 = (const float*)d_in[9];
    const float* msg_b1 = (const float*)d_in[10];
    const float* msg_w2 = (const float*)d_in[11];
    const float* msg_b2 = (const float*)d_in[12];
    const float* upd_w1 = (const float*)d_in[13];
    const float* upd_b1 = (const float*)d_in[14];
    const float* upd_w2 = (const float*)d_in[15];
    const float* upd_b2 = (const float*)d_in[16];
    const float* in_gamma = (const float*)d_in[17];
    const float* in_beta = (const float*)d_in[18];
    const float* blk_conv1 = (const float*)d_in[19];
    const float* blk_bn1_g = (const float*)d_in[20];
    const float* blk_bn1_b = (const float*)d_in[21];
    const float* blk_conv2 = (const float*)d_in[22];
    const float* blk_bn2_g = (const float*)d_in[23];
    const float* blk_bn2_b = (const float*)d_in[24];
    const float* blk_conv5 = (const float*)d_in[25];
    const float* blk_bns_g = (const float*)d_in[26];
    const float* blk_bns_b = (const float*)d_in[27];
    const float* fc_w = (const float*)d_in[28];
    const float* fc_b = (const float*)d_in[29];
    float* out = (float*)d_out;

    float *bufA, *bufB, *bufD, *nodeA, *Cm, *dv;
    __nv_bfloat16 *xhiA, *xloA, *xhiB, *xloB, *ahi, *alo;
    __nv_bfloat16 *W1hi, *W1lo, *W2hi, *W2lo, *W5hi, *W5lo;
    cudaGetSymbolAddress((void**)&bufA, g_bufA);
    cudaGetSymbolAddress((void**)&bufB, g_bufB);
    cudaGetSymbolAddress((void**)&bufD, g_bufD);
    cudaGetSymbolAddress((void**)&nodeA, g_nodeA);
    cudaGetSymbolAddress((void**)&Cm, g_C);
    cudaGetSymbolAddress((void**)&dv, g_d);
    cudaGetSymbolAddress((void**)&xhiA, g_xhiA);
    cudaGetSymbolAddress((void**)&xloA, g_xloA);
    cudaGetSymbolAddress((void**)&xhiB, g_xhiB);
    cudaGetSymbolAddress((void**)&xloB, g_xloB);
    cudaGetSymbolAddress((void**)&ahi, g_ahi);
    cudaGetSymbolAddress((void**)&alo, g_alo);
    cudaGetSymbolAddress((void**)&W1hi, g_W1hi);
    cudaGetSymbolAddress((void**)&W1lo, g_W1lo);
    cudaGetSymbolAddress((void**)&W2hi, g_W2hi);
    cudaGetSymbolAddress((void**)&W2lo, g_W2lo);
    cudaGetSymbolAddress((void**)&W5hi, g_W5hi);
    cudaGetSymbolAddress((void**)&W5lo, g_W5lo);

    const int SMEM_GEMM = (64 * 128 + 128 * 128) * 4;
    const int SMEM_EDGE = (8192 + 8192 + 384) * 4 + 64 * 4;

    cudaFuncSetAttribute(combo_gemm, cudaFuncAttributeMaxDynamicSharedMemorySize, SMEM_GEMM);
    cudaFuncSetAttribute(fused_mlp, cudaFuncAttributeMaxDynamicSharedMemorySize, SMEM_GEMM);
    cudaFuncSetAttribute(edge_kernel, cudaFuncAttributeMaxDynamicSharedMemorySize, SMEM_EDGE);
    cudaFuncSetAttribute(conv_mma<3, E_RELU_SPLIT>, cudaFuncAttributeMaxDynamicSharedMemorySize, C_SMEM);
    cudaFuncSetAttribute(conv_mma<3, E_ADDRELU_SPLIT_F32>, cudaFuncAttributeMaxDynamicSharedMemorySize, C_SMEM);
    cudaFuncSetAttribute(conv_mma<5, E_F32>, cudaFuncAttributeMaxDynamicSharedMemorySize, C_SMEM);

    // 0: Cm + nodeA + dvec + conv weight prep (merged)
    combo_gemm<<<611, 256, SMEM_GEMM>>>(node_embedding, edge_w2, msg_w1, edge_b2,
                                        msg_b1, Cm, nodeA, dv,
                                        blk_conv1, blk_bn1_g, blk_conv2, blk_bn2_g,
                                        blk_conv5, blk_bns_g, W1hi, W1lo, W2hi, W2lo,
                                        W5hi, W5lo);
    // 1: edges -> agg
    edge_kernel<<<1024, 256, SMEM_EDGE>>>(node_pos, grid_pos, edge_row, edge_col,
                                          edge_w1, edge_b1, Cm, dv, nodeA, bufA);
    // 2: fused grid MLP chain -> BN -> hi/lo split
    fused_mlp<<<128, 256, SMEM_GEMM>>>(bufA, msg_w2, msg_b2, upd_w1, upd_b1,
                                       upd_w2, upd_b2, in_gamma, in_beta, xhiA, xloA);

    // 3..11: 3 residual blocks (conv5 first => launch index 3 is profiled by ncu)
    __nv_bfloat16 *xh = xhiA, *xl = xloA, *nh = xhiB, *nl = xloB;
    for (int i = 0; i < 3; ++i) {
        conv_mma<5, E_F32><<<128, 256, C_SMEM>>>(
            xh, xl, W5hi + (size_t)i * 125 * 16384, W5lo + (size_t)i * 125 * 16384,
            blk_bns_b + i * 128, nullptr, bufB, nullptr, nullptr);
        conv_mma<3, E_RELU_SPLIT><<<128, 256, C_SMEM>>>(
            xh, xl, W1hi + (size_t)i * 27 * 16384, W1lo + (size_t)i * 27 * 16384,
            blk_bn1_b + i * 128, nullptr, nullptr, ahi, alo);
        conv_mma<3, E_ADDRELU_SPLIT_F32><<<128, 256, C_SMEM>>>(
            ahi, alo, W2hi + (size_t)i * 27 * 16384, W2lo + (size_t)i * 27 * 16384,
            blk_bn2_b + i * 128, bufB, bufD, nh, nl);
        __nv_bfloat16* t;
        t = xh; xh = nh; nh = t;
        t = xl; xl = nl; nl = t;
    }

    // 12: pool + fc + log_softmax
    pool_fc_kernel<<<2, 512>>>(bufD, fc_w, fc_b, out);
    (void)in_sizes; (void)n_in; (void)out_size;
}